// round 9
// baseline (speedup 1.0000x reference)
#include <cuda_runtime.h>
#include <cuda_bf16.h>
#include <mma.h>
#include <cstdint>

using namespace nvcuda;

#define NN   25000
#define EE   400000
#define FIN  256
#define CC   32
#define AA   9
#define WN   288     // CC*AA
#define BB   8
#define HH   64
#define SSP  4
#define FOUT 256
#define NTILE (EE / 64)   // 6250

__device__ float g_h[NN * CC];      // 3.2 MB
__device__ float g_agg[NN * WN];    // 28.8 MB
__device__ int   g_cnt[NN];
__device__ int   g_perm[EE];
// pre-split Wsc [1024][256] bf16 hi/lo (k_sc_mm)
__device__ __nv_bfloat16 g_Bhi[1024 * 256];
__device__ __nv_bfloat16 g_Blo[1024 * 256];
// pre-split Wm3 [64][288] bf16 hi/lo (k_w_tp)
__device__ __nv_bfloat16 g_W3hi[64 * 288];
__device__ __nv_bfloat16 g_W3lo[64 * 288];
// h2 activations [E][64] bf16 hi/lo
__device__ __nv_bfloat16 g_h2hi[EE * 64];
__device__ __nv_bfloat16 g_h2lo[EE * 64];

__device__ __forceinline__ float silu_f(float v) {
    return v / (1.0f + __expf(-v));
}

// ---------------------------------------------------------------------------
__global__ void k_zero() {
    int i = blockIdx.x * blockDim.x + threadIdx.x;
    int stride = gridDim.x * blockDim.x;
    float4* p = (float4*)g_agg;
    const int n4 = (NN * WN) / 4;
    float4 z = make_float4(0.f, 0.f, 0.f, 0.f);
    for (int k = i; k < n4; k += stride) p[k] = z;
    for (int k = i; k < NN; k += stride) g_cnt[k] = 0;
}

// ---------------------------------------------------------------------------
// counting sort by dst
// ---------------------------------------------------------------------------
__global__ void k_hist(const int* __restrict__ dstG) {
    int i = blockIdx.x * blockDim.x + threadIdx.x;
    int stride = gridDim.x * blockDim.x;
    for (int e = i; e < EE; e += stride) atomicAdd(&g_cnt[dstG[e]], 1);
}

__global__ void __launch_bounds__(1024) k_scan() {
    __shared__ int smv[1024];
    const int CH = 25;
    int t = threadIdx.x;
    int base = t * CH;
    int v[CH];
    int s = 0;
#pragma unroll
    for (int i = 0; i < CH; i++) {
        int idx = base + i;
        v[i] = (idx < NN) ? g_cnt[idx] : 0;
        s += v[i];
    }
    smv[t] = s;
    __syncthreads();
    for (int off = 1; off < 1024; off <<= 1) {
        int x = (t >= off) ? smv[t - off] : 0;
        __syncthreads();
        smv[t] += x;
        __syncthreads();
    }
    int ex = (t > 0) ? smv[t - 1] : 0;
#pragma unroll
    for (int i = 0; i < CH; i++) {
        int idx = base + i;
        if (idx < NN) g_cnt[idx] = ex;
        ex += v[i];
    }
}

__global__ void k_place(const int* __restrict__ dstG) {
    int i = blockIdx.x * blockDim.x + threadIdx.x;
    int stride = gridDim.x * blockDim.x;
    for (int e = i; e < EE; e += stride) {
        int pos = atomicAdd(&g_cnt[dstG[e]], 1);
        g_perm[pos] = e;
    }
}

// ---------------------------------------------------------------------------
// h = 0.25 * (x @ W1)    [NN, CC]
// ---------------------------------------------------------------------------
__global__ void __launch_bounds__(256) k_h(const float* __restrict__ x,
                                           const float* __restrict__ W1) {
    __shared__ float sW1[FIN * CC];
    __shared__ float sX[8][FIN];
    int t = threadIdx.x;
    int n0 = blockIdx.x * 8;
    for (int i = t; i < FIN * CC; i += 256) sW1[i] = W1[i];
    for (int i = t; i < 8 * FIN; i += 256)
        sX[i >> 8][i & 255] = x[(n0 + (i >> 8)) * FIN + (i & 255)];
    __syncthreads();
    int ty = t >> 5, tx = t & 31;
    float acc = 0.f;
#pragma unroll 8
    for (int f = 0; f < FIN; f++) acc += sX[ty][f] * sW1[f * CC + tx];
    g_h[(n0 + ty) * CC + tx] = 0.25f * acc;
}

// ---------------------------------------------------------------------------
// weight splits
// ---------------------------------------------------------------------------
__global__ void k_bsplit(const float* __restrict__ Wsc) {
    int idx = blockIdx.x * blockDim.x + threadIdx.x;
    if (idx >= 1024 * 256) return;
    float v = Wsc[idx];
    __nv_bfloat16 hi = __float2bfloat16(v);
    g_Bhi[idx] = hi;
    g_Blo[idx] = __float2bfloat16(v - __bfloat162float(hi));
}

__global__ void k_w3split(const float* __restrict__ Wm3) {
    int idx = blockIdx.x * blockDim.x + threadIdx.x;
    if (idx >= 64 * 288) return;
    float v = Wm3[idx];
    __nv_bfloat16 hi = __float2bfloat16(v);
    g_W3hi[idx] = hi;
    g_W3lo[idx] = __float2bfloat16(v - __bfloat162float(hi));
}

// ---------------------------------------------------------------------------
// tensor-core k_sc (R8, proven): out = xa @ Wsc, bf16 split
// ---------------------------------------------------------------------------
#define ASTR 40
#define BSTR 264

__global__ void __launch_bounds__(256) k_sc_mm(const float* __restrict__ x,
                                               const float* __restrict__ attrs,
                                               float* __restrict__ out) {
    extern __shared__ char smem[];
    __nv_bfloat16* sAhi = (__nv_bfloat16*)smem;
    __nv_bfloat16* sAlo = sAhi + 64 * ASTR;
    __nv_bfloat16* sBhi = sAlo + 64 * ASTR;
    __nv_bfloat16* sBlo = sBhi + 32 * BSTR;
    float* sOut = (float*)smem;

    int t = threadIdx.x;
    int wid = t >> 5;
    int warp_m = wid >> 2;
    int warp_n = wid & 3;
    int n0 = blockIdx.x * 64;

    wmma::fragment<wmma::accumulator, 16, 16, 16, float> acc[2][4];
#pragma unroll
    for (int im = 0; im < 2; im++)
#pragma unroll
        for (int jn = 0; jn < 4; jn++) wmma::fill_fragment(acc[im][jn], 0.0f);

    for (int kc = 0; kc < FIN * SSP; kc += 32) {
        for (int i = t; i < 64 * 32; i += 256) {
            int n = i >> 5, kk = i & 31;
            int k = kc + kk;
            int nn = n0 + n;
            float a = 0.f;
            if (nn < NN) a = x[nn * FIN + (k >> 2)] * attrs[nn * SSP + (k & 3)];
            __nv_bfloat16 hi = __float2bfloat16(a);
            sAhi[n * ASTR + kk] = hi;
            sAlo[n * ASTR + kk] = __float2bfloat16(a - __bfloat162float(hi));
        }
        for (int i = t; i < 32 * 256; i += 256) {
            int r = i >> 8, c = i & 255;
            sBhi[r * BSTR + c] = g_Bhi[(kc + r) * 256 + c];
            sBlo[r * BSTR + c] = g_Blo[(kc + r) * 256 + c];
        }
        __syncthreads();

#pragma unroll
        for (int kf = 0; kf < 2; kf++) {
            wmma::fragment<wmma::matrix_a, 16, 16, 16, __nv_bfloat16,
                           wmma::row_major> ahi[2], alo[2];
#pragma unroll
            for (int im = 0; im < 2; im++) {
                wmma::load_matrix_sync(ahi[im],
                    sAhi + (warp_m * 32 + 16 * im) * ASTR + kf * 16, ASTR);
                wmma::load_matrix_sync(alo[im],
                    sAlo + (warp_m * 32 + 16 * im) * ASTR + kf * 16, ASTR);
            }
#pragma unroll
            for (int jn = 0; jn < 4; jn++) {
                wmma::fragment<wmma::matrix_b, 16, 16, 16, __nv_bfloat16,
                               wmma::row_major> bhi, blo;
                wmma::load_matrix_sync(bhi,
                    sBhi + (kf * 16) * BSTR + warp_n * 64 + 16 * jn, BSTR);
                wmma::load_matrix_sync(blo,
                    sBlo + (kf * 16) * BSTR + warp_n * 64 + 16 * jn, BSTR);
#pragma unroll
                for (int im = 0; im < 2; im++) {
                    wmma::mma_sync(acc[im][jn], ahi[im], bhi, acc[im][jn]);
                    wmma::mma_sync(acc[im][jn], ahi[im], blo, acc[im][jn]);
                    wmma::mma_sync(acc[im][jn], alo[im], bhi, acc[im][jn]);
                }
            }
        }
        __syncthreads();
    }

    for (int half = 0; half < 2; half++) {
        if (warp_m == half) {
#pragma unroll
            for (int im = 0; im < 2; im++)
#pragma unroll
                for (int jn = 0; jn < 4; jn++)
                    wmma::store_matrix_sync(
                        sOut + (16 * im) * BSTR + warp_n * 64 + 16 * jn,
                        acc[im][jn], BSTR, wmma::mem_row_major);
        }
        __syncthreads();
        for (int i = t; i < 32 * 256; i += 256) {
            int r = i >> 8, c = i & 255;
            int nn = n0 + half * 32 + r;
            if (nn < NN) out[(long long)nn * FOUT + c] = sOut[r * BSTR + c];
        }
        __syncthreads();
    }
}

// ---------------------------------------------------------------------------
// k_mlp12: h2 = silu(silu(ee@Wm1)@Wm2), output bf16 hi/lo to global
// 64 edges/tile, 256 threads, persistent
// ---------------------------------------------------------------------------
#define ACTP 65

__global__ void __launch_bounds__(256) k_mlp12(const float* __restrict__ eeG,
                                               const float* __restrict__ Wm1,
                                               const float* __restrict__ Wm2) {
    __shared__ float sWm1[512];
    __shared__ float sWm2[4096];
    __shared__ float sEE[64 * BB];
    __shared__ float sAct[64 * ACTP];
    int t = threadIdx.x;
    for (int i = t; i < 512;  i += 256) sWm1[i] = Wm1[i];
    for (int i = t; i < 4096; i += 256) sWm2[i] = Wm2[i];

    const int e2 = t >> 2;          // edge 0..63
    const int j0 = (t & 3) * 16;    // out group

    for (int tile = blockIdx.x; tile < NTILE; tile += gridDim.x) {
        int e0 = tile * 64;
        __syncthreads();   // protects sEE/sAct reuse across iterations
        for (int i = t; i < 64 * BB; i += 256) sEE[i] = eeG[e0 * BB + i];
        __syncthreads();

        // phase 1
        {
            float acc[16];
#pragma unroll
            for (int j = 0; j < 16; j++) acc[j] = 0.f;
#pragma unroll
            for (int b = 0; b < BB; b++) {
                float v = sEE[e2 * BB + b];
#pragma unroll
                for (int j = 0; j < 16; j++) acc[j] += v * sWm1[b * HH + j0 + j];
            }
#pragma unroll
            for (int j = 0; j < 16; j++) sAct[e2 * ACTP + j0 + j] = silu_f(acc[j]);
        }
        __syncthreads();

        // phase 2 -> global bf16 split (packed u32 stores)
        {
            float acc[16];
#pragma unroll
            for (int j = 0; j < 16; j++) acc[j] = 0.f;
#pragma unroll 8
            for (int k = 0; k < HH; k++) {
                float v = sAct[e2 * ACTP + k];
#pragma unroll
                for (int j = 0; j < 16; j++) acc[j] += v * sWm2[k * HH + j0 + j];
            }
            uint32_t* dh = (uint32_t*)&g_h2hi[(long long)(e0 + e2) * 64 + j0];
            uint32_t* dl = (uint32_t*)&g_h2lo[(long long)(e0 + e2) * 64 + j0];
#pragma unroll
            for (int jp = 0; jp < 8; jp++) {
                float v0 = silu_f(acc[2 * jp]);
                float v1 = silu_f(acc[2 * jp + 1]);
                __nv_bfloat16 h0 = __float2bfloat16(v0);
                __nv_bfloat16 h1 = __float2bfloat16(v1);
                __nv_bfloat16 l0 = __float2bfloat16(v0 - __bfloat162float(h0));
                __nv_bfloat16 l1 = __float2bfloat16(v1 - __bfloat162float(h1));
                dh[jp] = (uint32_t)__bfloat16_as_ushort(h0) |
                         ((uint32_t)__bfloat16_as_ushort(h1) << 16);
                dl[jp] = (uint32_t)__bfloat16_as_ushort(l0) |
                         ((uint32_t)__bfloat16_as_ushort(l1) << 16);
            }
        }
    }
}

// ---------------------------------------------------------------------------
// k_w_tp: per 64 sorted edges — w = h2 @ Wm3 (wmma bf16 split), then
// TP epilogue + run-length scatter. 288 threads (9 warps), thread t owns o=t.
// ---------------------------------------------------------------------------
#define H2STR 72   // A smem stride (bf16)
#define WSTR  296  // w smem stride (fp32)

__global__ void __launch_bounds__(288) k_w_tp(const float* __restrict__ shG,
                                              const int* __restrict__ dstG,
                                              const int* __restrict__ srcG) {
    extern __shared__ char smem[];
    __nv_bfloat16* sAhi = (__nv_bfloat16*)smem;          // 64*72*2 = 9216 B
    __nv_bfloat16* sAlo = sAhi + 64 * H2STR;             // 9216 B
    float* sW  = (float*)(sAlo + 64 * H2STR);            // 64*296*4 = 75776 B
    float* sHs = sW + 64 * WSTR;                         // 8192 B
    float* sSH = sHs + 64 * CC;                          // 2304 B
    int* sDst = (int*)(sSH + 64 * AA);
    int* sSrc = sDst + 64;
    int* sEid = sSrc + 64;

    int t = threadIdx.x;
    int wid = t >> 5;                // 0..8
    int e0 = blockIdx.x * 64;

    if (t < 64) {
        int eg = g_perm[e0 + t];
        sEid[t] = eg;
        sDst[t] = dstG[eg];
        sSrc[t] = srcG[eg];
    }
    __syncthreads();

    // gather h2 rows (32 u32 per row) + h[src] + sh
    for (int i = t; i < 64 * 32; i += 288) {
        int r = i >> 5, c = i & 31;
        ((uint32_t*)(sAhi + r * H2STR))[c] =
            ((const uint32_t*)g_h2hi)[(long long)sEid[r] * 32 + c];
        ((uint32_t*)(sAlo + r * H2STR))[c] =
            ((const uint32_t*)g_h2lo)[(long long)sEid[r] * 32 + c];
        sHs[r * CC + c] = g_h[sSrc[r] * CC + c];
    }
    for (int i = t; i < 64 * AA; i += 288) {
        int e = i / AA, a = i - AA * e;
        sSH[i] = shG[(long long)sEid[e] * AA + a];
    }
    __syncthreads();

    // GEMM: w[64, 288] = A[64, 64] @ Wm3[64, 288]; warp wid owns N cols [32w, 32w+32)
    {
        wmma::fragment<wmma::accumulator, 16, 16, 16, float> acc[4][2];
#pragma unroll
        for (int im = 0; im < 4; im++)
#pragma unroll
            for (int jn = 0; jn < 2; jn++) wmma::fill_fragment(acc[im][jn], 0.0f);

#pragma unroll
        for (int kf = 0; kf < 4; kf++) {
            wmma::fragment<wmma::matrix_a, 16, 16, 16, __nv_bfloat16,
                           wmma::row_major> ahi[4], alo[4];
#pragma unroll
            for (int im = 0; im < 4; im++) {
                wmma::load_matrix_sync(ahi[im],
                    sAhi + (16 * im) * H2STR + kf * 16, H2STR);
                wmma::load_matrix_sync(alo[im],
                    sAlo + (16 * im) * H2STR + kf * 16, H2STR);
            }
#pragma unroll
            for (int jn = 0; jn < 2; jn++) {
                wmma::fragment<wmma::matrix_b, 16, 16, 16, __nv_bfloat16,
                               wmma::row_major> bhi, blo;
                const __nv_bfloat16* bp = g_W3hi + (kf * 16) * WN + wid * 32 + 16 * jn;
                const __nv_bfloat16* blp = g_W3lo + (kf * 16) * WN + wid * 32 + 16 * jn;
                wmma::load_matrix_sync(bhi, bp, WN);
                wmma::load_matrix_sync(blo, blp, WN);
#pragma unroll
                for (int im = 0; im < 4; im++) {
                    wmma::mma_sync(acc[im][jn], ahi[im], bhi, acc[im][jn]);
                    wmma::mma_sync(acc[im][jn], ahi[im], blo, acc[im][jn]);
                    wmma::mma_sync(acc[im][jn], alo[im], bhi, acc[im][jn]);
                }
            }
        }
#pragma unroll
        for (int im = 0; im < 4; im++)
#pragma unroll
            for (int jn = 0; jn < 2; jn++)
                wmma::store_matrix_sync(
                    sW + (16 * im) * WSTR + wid * 32 + 16 * jn,
                    acc[im][jn], WSTR, wmma::mem_row_major);
    }
    __syncthreads();

    // epilogue: thread t owns output column o = t; run-length scatter
    {
        const int c = t / AA;
        const int a = t - AA * c;
        float racc = 0.f;
        int cur = sDst[0];
#pragma unroll 8
        for (int e = 0; e < 64; e++) {
            int d = sDst[e];
            if (d != cur) {
                atomicAdd(&g_agg[(long long)cur * WN + t], racc);
                racc = 0.f;
                cur = d;
            }
            racc += sW[e * WSTR + t] * sHs[e * CC + c] * sSH[e * AA + a];
        }
        atomicAdd(&g_agg[(long long)cur * WN + t], racc);
    }
}

// ---------------------------------------------------------------------------
// out = silu(agg @ W2) + sc_out (R1 scalar)
// ---------------------------------------------------------------------------
__global__ void __launch_bounds__(256) k_final(const float* __restrict__ W2,
                                               float* __restrict__ out) {
    __shared__ float sA[32][65];
    __shared__ float sB[32][64];
    int t = threadIdx.x;
    int n0 = blockIdx.x * 64;
    int o0 = blockIdx.y * 64;
    int tr = t >> 4, tc = t & 15;
    float acc[4][4];
#pragma unroll
    for (int i = 0; i < 4; i++)
#pragma unroll
        for (int j = 0; j < 4; j++) acc[i][j] = 0.f;

    for (int kc = 0; kc < WN; kc += 32) {
        for (int i = t; i < 64 * 32; i += 256) {
            int n = i >> 5, kk = i & 31;
            int nn = n0 + n;
            sA[kk][n] = (nn < NN) ? g_agg[(long long)nn * WN + kc + kk] : 0.f;
        }
        for (int i = t; i < 32 * 64; i += 256) {
            int kk = i >> 6, o = i & 63;
            sB[kk][o] = W2[(kc + kk) * FOUT + o0 + o];
        }
        __syncthreads();
#pragma unroll 8
        for (int k = 0; k < 32; k++) {
            float a[4], b[4];
#pragma unroll
            for (int i = 0; i < 4; i++) a[i] = sA[k][tr * 4 + i];
#pragma unroll
            for (int j = 0; j < 4; j++) b[j] = sB[k][tc * 4 + j];
#pragma unroll
            for (int i = 0; i < 4; i++)
#pragma unroll
                for (int j = 0; j < 4; j++) acc[i][j] += a[i] * b[j];
        }
        __syncthreads();
    }
#pragma unroll
    for (int i = 0; i < 4; i++) {
        int nn = n0 + tr * 4 + i;
        if (nn >= NN) continue;
#pragma unroll
        for (int j = 0; j < 4; j++) {
            int o = o0 + tc * 4 + j;
            out[nn * FOUT + o] = silu_f(acc[i][j]) + out[nn * FOUT + o];
        }
    }
}

// ---------------------------------------------------------------------------
extern "C" void kernel_launch(void* const* d_in, const int* in_sizes, int n_in,
                              void* d_out, int out_size) {
    const float* x     = (const float*)d_in[0];
    const float* attrs = (const float*)d_in[1];
    const float* ee    = (const float*)d_in[2];
    const float* sh    = (const float*)d_in[3];
    const int*   eidx  = (const int*)d_in[4];
    const float* W1    = (const float*)d_in[5];
    const float* Wm1   = (const float*)d_in[6];
    const float* Wm2   = (const float*)d_in[7];
    const float* Wm3   = (const float*)d_in[8];
    const float* W2    = (const float*)d_in[9];
    const float* Wsc   = (const float*)d_in[10];
    float* out = (float*)d_out;

    const int* dst = eidx;
    const int* src = eidx + EE;

    k_zero<<<1024, 256>>>();
    k_hist<<<400, 256>>>(dst);
    k_scan<<<1, 1024>>>();
    k_place<<<400, 256>>>(dst);

    k_h<<<NN / 8, 256>>>(x, W1);
    k_bsplit<<<1024, 256>>>(Wsc);
    k_w3split<<<72, 256>>>(Wm3);

    const int sc_smem = (2 * 64 * ASTR + 2 * 32 * BSTR) * 2 + 256;
    cudaFuncSetAttribute(k_sc_mm, cudaFuncAttributeMaxDynamicSharedMemorySize, sc_smem);
    k_sc_mm<<<(NN + 63) / 64, 256, sc_smem>>>(x, attrs, out);

    k_mlp12<<<912, 256>>>(ee, Wm1, Wm2);

    const int wtp_smem = 2 * 64 * H2STR * 2 + 64 * WSTR * 4 +
                         64 * CC * 4 + 64 * AA * 4 + 3 * 64 * 4 + 256;
    cudaFuncSetAttribute(k_w_tp, cudaFuncAttributeMaxDynamicSharedMemorySize, wtp_smem);
    k_w_tp<<<NTILE, 288, wtp_smem>>>(sh, dst, src);

    dim3 gf((NN + 63) / 64, 4);
    k_final<<<gf, 256>>>(W2, out);
}

// round 10
// speedup vs baseline: 1.0741x; 1.0741x over previous
#include <cuda_runtime.h>
#include <cuda_bf16.h>
#include <mma.h>
#include <cstdint>

using namespace nvcuda;

#define NN   25000
#define EE   400000
#define FIN  256
#define CC   32
#define AA   9
#define WN   288     // CC*AA
#define BB   8
#define HH   64
#define SSP  4
#define FOUT 256
#define NTILE (EE / 64)   // 6250

__device__ float g_h[NN * CC];      // 3.2 MB
__device__ float g_agg[NN * WN];    // 28.8 MB
__device__ int   g_cnt[NN];
__device__ int   g_perm[EE];
// pre-split Wsc [1024][256] bf16 hi/lo (k_sc_mm)
__device__ __nv_bfloat16 g_Bhi[1024 * 256];
__device__ __nv_bfloat16 g_Blo[1024 * 256];
// pre-split Wm3 [64][288] bf16 hi/lo (k_edge phase 3)
__device__ __nv_bfloat16 g_W3hi[64 * 288];
__device__ __nv_bfloat16 g_W3lo[64 * 288];
// pre-split W2 [288][256] bf16 hi/lo (k_final_mm)
__device__ __nv_bfloat16 g_W2hi[288 * 256];
__device__ __nv_bfloat16 g_W2lo[288 * 256];

__device__ __forceinline__ float silu_f(float v) {
    return v / (1.0f + __expf(-v));
}

// ---------------------------------------------------------------------------
__global__ void k_zero() {
    int i = blockIdx.x * blockDim.x + threadIdx.x;
    int stride = gridDim.x * blockDim.x;
    float4* p = (float4*)g_agg;
    const int n4 = (NN * WN) / 4;
    float4 z = make_float4(0.f, 0.f, 0.f, 0.f);
    for (int k = i; k < n4; k += stride) p[k] = z;
    for (int k = i; k < NN; k += stride) g_cnt[k] = 0;
}

// ---------------------------------------------------------------------------
// counting sort by dst
// ---------------------------------------------------------------------------
__global__ void k_hist(const int* __restrict__ dstG) {
    int i = blockIdx.x * blockDim.x + threadIdx.x;
    int stride = gridDim.x * blockDim.x;
    for (int e = i; e < EE; e += stride) atomicAdd(&g_cnt[dstG[e]], 1);
}

__global__ void __launch_bounds__(1024) k_scan() {
    __shared__ int smv[1024];
    const int CH = 25;
    int t = threadIdx.x;
    int base = t * CH;
    int v[CH];
    int s = 0;
#pragma unroll
    for (int i = 0; i < CH; i++) {
        int idx = base + i;
        v[i] = (idx < NN) ? g_cnt[idx] : 0;
        s += v[i];
    }
    smv[t] = s;
    __syncthreads();
    for (int off = 1; off < 1024; off <<= 1) {
        int x = (t >= off) ? smv[t - off] : 0;
        __syncthreads();
        smv[t] += x;
        __syncthreads();
    }
    int ex = (t > 0) ? smv[t - 1] : 0;
#pragma unroll
    for (int i = 0; i < CH; i++) {
        int idx = base + i;
        if (idx < NN) g_cnt[idx] = ex;
        ex += v[i];
    }
}

__global__ void k_place(const int* __restrict__ dstG) {
    int i = blockIdx.x * blockDim.x + threadIdx.x;
    int stride = gridDim.x * blockDim.x;
    for (int e = i; e < EE; e += stride) {
        int pos = atomicAdd(&g_cnt[dstG[e]], 1);
        g_perm[pos] = e;
    }
}

// ---------------------------------------------------------------------------
// h = 0.25 * (x @ W1)    [NN, CC]
// ---------------------------------------------------------------------------
__global__ void __launch_bounds__(256) k_h(const float* __restrict__ x,
                                           const float* __restrict__ W1) {
    __shared__ float sW1[FIN * CC];
    __shared__ float sX[8][FIN];
    int t = threadIdx.x;
    int n0 = blockIdx.x * 8;
    for (int i = t; i < FIN * CC; i += 256) sW1[i] = W1[i];
    for (int i = t; i < 8 * FIN; i += 256)
        sX[i >> 8][i & 255] = x[(n0 + (i >> 8)) * FIN + (i & 255)];
    __syncthreads();
    int ty = t >> 5, tx = t & 31;
    float acc = 0.f;
#pragma unroll 8
    for (int f = 0; f < FIN; f++) acc += sX[ty][f] * sW1[f * CC + tx];
    g_h[(n0 + ty) * CC + tx] = 0.25f * acc;
}

// ---------------------------------------------------------------------------
// weight splits
// ---------------------------------------------------------------------------
__global__ void k_bsplit(const float* __restrict__ Wsc) {
    int idx = blockIdx.x * blockDim.x + threadIdx.x;
    if (idx >= 1024 * 256) return;
    float v = Wsc[idx];
    __nv_bfloat16 hi = __float2bfloat16(v);
    g_Bhi[idx] = hi;
    g_Blo[idx] = __float2bfloat16(v - __bfloat162float(hi));
}

__global__ void k_w3split(const float* __restrict__ Wm3) {
    int idx = blockIdx.x * blockDim.x + threadIdx.x;
    if (idx >= 64 * 288) return;
    float v = Wm3[idx];
    __nv_bfloat16 hi = __float2bfloat16(v);
    g_W3hi[idx] = hi;
    g_W3lo[idx] = __float2bfloat16(v - __bfloat162float(hi));
}

__global__ void k_w2split(const float* __restrict__ W2) {
    int idx = blockIdx.x * blockDim.x + threadIdx.x;
    if (idx >= 288 * 256) return;
    float v = W2[idx];
    __nv_bfloat16 hi = __float2bfloat16(v);
    g_W2hi[idx] = hi;
    g_W2lo[idx] = __float2bfloat16(v - __bfloat162float(hi));
}

// ---------------------------------------------------------------------------
// tensor-core k_sc (R8, proven): out = xa @ Wsc, bf16 split
// ---------------------------------------------------------------------------
#define ASTR 40
#define BSTR 264

__global__ void __launch_bounds__(256) k_sc_mm(const float* __restrict__ x,
                                               const float* __restrict__ attrs,
                                               float* __restrict__ out) {
    extern __shared__ char smem[];
    __nv_bfloat16* sAhi = (__nv_bfloat16*)smem;
    __nv_bfloat16* sAlo = sAhi + 64 * ASTR;
    __nv_bfloat16* sBhi = sAlo + 64 * ASTR;
    __nv_bfloat16* sBlo = sBhi + 32 * BSTR;
    float* sOut = (float*)smem;

    int t = threadIdx.x;
    int wid = t >> 5;
    int warp_m = wid >> 2;
    int warp_n = wid & 3;
    int n0 = blockIdx.x * 64;

    wmma::fragment<wmma::accumulator, 16, 16, 16, float> acc[2][4];
#pragma unroll
    for (int im = 0; im < 2; im++)
#pragma unroll
        for (int jn = 0; jn < 4; jn++) wmma::fill_fragment(acc[im][jn], 0.0f);

    for (int kc = 0; kc < FIN * SSP; kc += 32) {
        for (int i = t; i < 64 * 32; i += 256) {
            int n = i >> 5, kk = i & 31;
            int k = kc + kk;
            int nn = n0 + n;
            float a = 0.f;
            if (nn < NN) a = x[nn * FIN + (k >> 2)] * attrs[nn * SSP + (k & 3)];
            __nv_bfloat16 hi = __float2bfloat16(a);
            sAhi[n * ASTR + kk] = hi;
            sAlo[n * ASTR + kk] = __float2bfloat16(a - __bfloat162float(hi));
        }
        for (int i = t; i < 32 * 256; i += 256) {
            int r = i >> 8, c = i & 255;
            sBhi[r * BSTR + c] = g_Bhi[(kc + r) * 256 + c];
            sBlo[r * BSTR + c] = g_Blo[(kc + r) * 256 + c];
        }
        __syncthreads();

#pragma unroll
        for (int kf = 0; kf < 2; kf++) {
            wmma::fragment<wmma::matrix_a, 16, 16, 16, __nv_bfloat16,
                           wmma::row_major> ahi[2], alo[2];
#pragma unroll
            for (int im = 0; im < 2; im++) {
                wmma::load_matrix_sync(ahi[im],
                    sAhi + (warp_m * 32 + 16 * im) * ASTR + kf * 16, ASTR);
                wmma::load_matrix_sync(alo[im],
                    sAlo + (warp_m * 32 + 16 * im) * ASTR + kf * 16, ASTR);
            }
#pragma unroll
            for (int jn = 0; jn < 4; jn++) {
                wmma::fragment<wmma::matrix_b, 16, 16, 16, __nv_bfloat16,
                               wmma::row_major> bhi, blo;
                wmma::load_matrix_sync(bhi,
                    sBhi + (kf * 16) * BSTR + warp_n * 64 + 16 * jn, BSTR);
                wmma::load_matrix_sync(blo,
                    sBlo + (kf * 16) * BSTR + warp_n * 64 + 16 * jn, BSTR);
#pragma unroll
                for (int im = 0; im < 2; im++) {
                    wmma::mma_sync(acc[im][jn], ahi[im], bhi, acc[im][jn]);
                    wmma::mma_sync(acc[im][jn], ahi[im], blo, acc[im][jn]);
                    wmma::mma_sync(acc[im][jn], alo[im], bhi, acc[im][jn]);
                }
            }
        }
        __syncthreads();
    }

    for (int half = 0; half < 2; half++) {
        if (warp_m == half) {
#pragma unroll
            for (int im = 0; im < 2; im++)
#pragma unroll
                for (int jn = 0; jn < 4; jn++)
                    wmma::store_matrix_sync(
                        sOut + (16 * im) * BSTR + warp_n * 64 + 16 * jn,
                        acc[im][jn], BSTR, wmma::mem_row_major);
        }
        __syncthreads();
        for (int i = t; i < 32 * 256; i += 256) {
            int r = i >> 8, c = i & 255;
            int nn = n0 + half * 32 + r;
            if (nn < NN) out[(long long)nn * FOUT + c] = sOut[r * BSTR + c];
        }
        __syncthreads();
    }
}

// ---------------------------------------------------------------------------
// fused edge kernel: 288 threads, persistent, dst-sorted 64-edge tiles
// phase 1/2 scalar MLP -> bf16 h2 in smem; phase 3 wmma GEMM + run-length scatter
// ---------------------------------------------------------------------------
#define ACTP  65
#define H2STR 72    // bf16 A stride
#define WSTR  292   // fp32 w stride (292 % 32 == 4 -> conflict-free)

// smem layout (bytes)
#define EO_W3HI 0
#define EO_W3LO (EO_W3HI + 64 * WN * 2)          // 36864
#define EO_AHI  (EO_W3LO + 64 * WN * 2)          // 73728
#define EO_ALO  (EO_AHI + 64 * H2STR * 2)        // 82944
#define EO_F    (EO_ALO + 64 * H2STR * 2)        // 92160 (float area)
// float offsets (in floats, relative to EO_F)
#define FO_WM1  0
#define FO_WM2  (FO_WM1 + 512)
#define FO_ACT  (FO_WM2 + 4096)
#define FO_HS   (FO_ACT + 64 * ACTP)
#define FO_EE   (FO_HS + 64 * CC)
#define FO_SH   (FO_EE + 64 * BB)
#define FO_W    (FO_SH + 64 * AA)
#define FO_END  (FO_W + 64 * WSTR)
#define EO_IDX  (EO_F + FO_END * 4)
#define EDGE_SMEM (EO_IDX + 3 * 64 * 4 + 16)

__global__ void __launch_bounds__(288, 1) k_edge(
    const float* __restrict__ eeG, const float* __restrict__ shG,
    const int* __restrict__ dstG, const int* __restrict__ srcG,
    const float* __restrict__ Wm1, const float* __restrict__ Wm2) {
    extern __shared__ char smem[];
    __nv_bfloat16* sW3hi = (__nv_bfloat16*)(smem + EO_W3HI);
    __nv_bfloat16* sW3lo = (__nv_bfloat16*)(smem + EO_W3LO);
    __nv_bfloat16* sAhi  = (__nv_bfloat16*)(smem + EO_AHI);
    __nv_bfloat16* sAlo  = (__nv_bfloat16*)(smem + EO_ALO);
    float* sf   = (float*)(smem + EO_F);
    float* sWm1 = sf + FO_WM1;
    float* sWm2 = sf + FO_WM2;
    float* sAct = sf + FO_ACT;
    float* sHs  = sf + FO_HS;
    float* sEE  = sf + FO_EE;
    float* sSH  = sf + FO_SH;
    float* sW   = sf + FO_W;
    int* sDst = (int*)(smem + EO_IDX);
    int* sSrc = sDst + 64;
    int* sEid = sSrc + 64;

    int t = threadIdx.x;
    int wid = t >> 5;   // 0..8

    for (int i = t; i < 512;  i += 288) sWm1[i] = Wm1[i];
    for (int i = t; i < 4096; i += 288) sWm2[i] = Wm2[i];
    // Wm3 bf16 hi/lo (u32 copies)
    for (int i = t; i < 64 * WN / 2; i += 288) {
        ((uint32_t*)sW3hi)[i] = ((const uint32_t*)g_W3hi)[i];
        ((uint32_t*)sW3lo)[i] = ((const uint32_t*)g_W3lo)[i];
    }
    __syncthreads();

    const int e2 = t >> 2;          // phase 1/2 edge (t < 256)
    const int j0 = (t & 3) * 16;
    const int oc = t / AA;          // epilogue: col c
    const int oa = t - AA * oc;     // epilogue: col a

    for (int tile = blockIdx.x; tile < NTILE; tile += gridDim.x) {
        int e0g = tile * 64;
        if (t < 64) {
            int eg = g_perm[e0g + t];
            sEid[t] = eg;
            sDst[t] = dstG[eg];
            sSrc[t] = srcG[eg];
        }
        __syncthreads();
        for (int i = t; i < 64 * BB; i += 288) {
            int e = i >> 3, b = i & 7;
            sEE[i] = eeG[(long long)sEid[e] * BB + b];
        }
        for (int i = t; i < 64 * AA; i += 288) {
            int e = i / AA, a = i - AA * e;
            sSH[i] = shG[(long long)sEid[e] * AA + a];
        }
        for (int i = t; i < 64 * CC; i += 288) {
            int e = i >> 5, c = i & 31;
            sHs[i] = g_h[sSrc[e] * CC + c];
        }
        __syncthreads();

        // phase 1: h1 = silu(ee @ Wm1) (first 256 threads)
        if (t < 256) {
            float acc[16];
#pragma unroll
            for (int j = 0; j < 16; j++) acc[j] = 0.f;
#pragma unroll
            for (int b = 0; b < BB; b++) {
                float v = sEE[e2 * BB + b];
#pragma unroll
                for (int j = 0; j < 16; j++) acc[j] += v * sWm1[b * HH + j0 + j];
            }
#pragma unroll
            for (int j = 0; j < 16; j++) sAct[e2 * ACTP + j0 + j] = silu_f(acc[j]);
        }
        __syncthreads();

        // phase 2: h2 = silu(h1 @ Wm2) -> bf16 hi/lo into sAhi/sAlo
        if (t < 256) {
            float acc[16];
#pragma unroll
            for (int j = 0; j < 16; j++) acc[j] = 0.f;
#pragma unroll 8
            for (int k = 0; k < HH; k++) {
                float v = sAct[e2 * ACTP + k];
#pragma unroll
                for (int j = 0; j < 16; j++) acc[j] += v * sWm2[k * HH + j0 + j];
            }
#pragma unroll
            for (int j = 0; j < 16; j++) {
                float v = silu_f(acc[j]);
                __nv_bfloat16 hi = __float2bfloat16(v);
                sAhi[e2 * H2STR + j0 + j] = hi;
                sAlo[e2 * H2STR + j0 + j] =
                    __float2bfloat16(v - __bfloat162float(hi));
            }
        }
        __syncthreads();

        // phase 3a: w[64,288] = h2 @ Wm3 (wmma bf16 split); warp wid -> cols [32wid,32wid+32)
        {
            wmma::fragment<wmma::accumulator, 16, 16, 16, float> acc[4][2];
#pragma unroll
            for (int im = 0; im < 4; im++)
#pragma unroll
                for (int jn = 0; jn < 2; jn++) wmma::fill_fragment(acc[im][jn], 0.0f);

#pragma unroll
            for (int kf = 0; kf < 4; kf++) {
                wmma::fragment<wmma::matrix_a, 16, 16, 16, __nv_bfloat16,
                               wmma::row_major> ahi[4], alo[4];
#pragma unroll
                for (int im = 0; im < 4; im++) {
                    wmma::load_matrix_sync(ahi[im],
                        sAhi + (16 * im) * H2STR + kf * 16, H2STR);
                    wmma::load_matrix_sync(alo[im],
                        sAlo + (16 * im) * H2STR + kf * 16, H2STR);
                }
#pragma unroll
                for (int jn = 0; jn < 2; jn++) {
                    wmma::fragment<wmma::matrix_b, 16, 16, 16, __nv_bfloat16,
                                   wmma::row_major> bhi, blo;
                    wmma::load_matrix_sync(bhi,
                        sW3hi + (kf * 16) * WN + wid * 32 + 16 * jn, WN);
                    wmma::load_matrix_sync(blo,
                        sW3lo + (kf * 16) * WN + wid * 32 + 16 * jn, WN);
#pragma unroll
                    for (int im = 0; im < 4; im++) {
                        wmma::mma_sync(acc[im][jn], ahi[im], bhi, acc[im][jn]);
                        wmma::mma_sync(acc[im][jn], ahi[im], blo, acc[im][jn]);
                        wmma::mma_sync(acc[im][jn], alo[im], bhi, acc[im][jn]);
                    }
                }
            }
#pragma unroll
            for (int im = 0; im < 4; im++)
#pragma unroll
                for (int jn = 0; jn < 2; jn++)
                    wmma::store_matrix_sync(
                        sW + (16 * im) * WSTR + wid * 32 + 16 * jn,
                        acc[im][jn], WSTR, wmma::mem_row_major);
        }
        __syncthreads();

        // phase 3b: TP epilogue — thread t owns col o=t; run-length scatter
        {
            float racc = 0.f;
            int cur = sDst[0];
#pragma unroll 8
            for (int e = 0; e < 64; e++) {
                int d = sDst[e];
                if (d != cur) {
                    atomicAdd(&g_agg[(long long)cur * WN + t], racc);
                    racc = 0.f;
                    cur = d;
                }
                racc += sW[e * WSTR + t] * sHs[e * CC + oc] * sSH[e * AA + oa];
            }
            atomicAdd(&g_agg[(long long)cur * WN + t], racc);
        }
        __syncthreads();
    }
}

// ---------------------------------------------------------------------------
// k_final_mm: out = silu(agg @ W2) + out, wmma bf16 split, K=288
// CTA: 64 nodes x 256 outs, 8 warps
// ---------------------------------------------------------------------------
__global__ void __launch_bounds__(256) k_final_mm(float* __restrict__ out) {
    extern __shared__ char smem[];
    __nv_bfloat16* sAhi = (__nv_bfloat16*)smem;
    __nv_bfloat16* sAlo = sAhi + 64 * ASTR;
    __nv_bfloat16* sBhi = sAlo + 64 * ASTR;
    __nv_bfloat16* sBlo = sBhi + 32 * BSTR;
    float* sOut = (float*)smem;

    int t = threadIdx.x;
    int wid = t >> 5;
    int warp_m = wid >> 2;
    int warp_n = wid & 3;
    int n0 = blockIdx.x * 64;

    wmma::fragment<wmma::accumulator, 16, 16, 16, float> acc[2][4];
#pragma unroll
    for (int im = 0; im < 2; im++)
#pragma unroll
        for (int jn = 0; jn < 4; jn++) wmma::fill_fragment(acc[im][jn], 0.0f);

    for (int kc = 0; kc < WN; kc += 32) {
        for (int i = t; i < 64 * 32; i += 256) {
            int n = i >> 5, kk = i & 31;
            int nn = n0 + n;
            float a = 0.f;
            if (nn < NN) a = g_agg[(long long)nn * WN + kc + kk];
            __nv_bfloat16 hi = __float2bfloat16(a);
            sAhi[n * ASTR + kk] = hi;
            sAlo[n * ASTR + kk] = __float2bfloat16(a - __bfloat162float(hi));
        }
        for (int i = t; i < 32 * 256; i += 256) {
            int r = i >> 8, c = i & 255;
            sBhi[r * BSTR + c] = g_W2hi[(kc + r) * 256 + c];
            sBlo[r * BSTR + c] = g_W2lo[(kc + r) * 256 + c];
        }
        __syncthreads();

#pragma unroll
        for (int kf = 0; kf < 2; kf++) {
            wmma::fragment<wmma::matrix_a, 16, 16, 16, __nv_bfloat16,
                           wmma::row_major> ahi[2], alo[2];
#pragma unroll
            for (int im = 0; im < 2; im++) {
                wmma::load_matrix_sync(ahi[im],
                    sAhi + (warp_m * 32 + 16 * im) * ASTR + kf * 16, ASTR);
                wmma::load_matrix_sync(alo[im],
                    sAlo + (warp_m * 32 + 16 * im) * ASTR + kf * 16, ASTR);
            }
#pragma unroll
            for (int jn = 0; jn < 4; jn++) {
                wmma::fragment<wmma::matrix_b, 16, 16, 16, __nv_bfloat16,
                               wmma::row_major> bhi, blo;
                wmma::load_matrix_sync(bhi,
                    sBhi + (kf * 16) * BSTR + warp_n * 64 + 16 * jn, BSTR);
                wmma::load_matrix_sync(blo,
                    sBlo + (kf * 16) * BSTR + warp_n * 64 + 16 * jn, BSTR);
#pragma unroll
                for (int im = 0; im < 2; im++) {
                    wmma::mma_sync(acc[im][jn], ahi[im], bhi, acc[im][jn]);
                    wmma::mma_sync(acc[im][jn], ahi[im], blo, acc[im][jn]);
                    wmma::mma_sync(acc[im][jn], alo[im], bhi, acc[im][jn]);
                }
            }
        }
        __syncthreads();
    }

    for (int half = 0; half < 2; half++) {
        if (warp_m == half) {
#pragma unroll
            for (int im = 0; im < 2; im++)
#pragma unroll
                for (int jn = 0; jn < 4; jn++)
                    wmma::store_matrix_sync(
                        sOut + (16 * im) * BSTR + warp_n * 64 + 16 * jn,
                        acc[im][jn], BSTR, wmma::mem_row_major);
        }
        __syncthreads();
        for (int i = t; i < 32 * 256; i += 256) {
            int r = i >> 8, c = i & 255;
            int nn = n0 + half * 32 + r;
            if (nn < NN) {
                long long o = (long long)nn * FOUT + c;
                out[o] = silu_f(sOut[r * BSTR + c]) + out[o];
            }
        }
        __syncthreads();
    }
}

// ---------------------------------------------------------------------------
extern "C" void kernel_launch(void* const* d_in, const int* in_sizes, int n_in,
                              void* d_out, int out_size) {
    const float* x     = (const float*)d_in[0];
    const float* attrs = (const float*)d_in[1];
    const float* ee    = (const float*)d_in[2];
    const float* sh    = (const float*)d_in[3];
    const int*   eidx  = (const int*)d_in[4];
    const float* W1    = (const float*)d_in[5];
    const float* Wm1   = (const float*)d_in[6];
    const float* Wm2   = (const float*)d_in[7];
    const float* Wm3   = (const float*)d_in[8];
    const float* W2    = (const float*)d_in[9];
    const float* Wsc   = (const float*)d_in[10];
    float* out = (float*)d_out;

    const int* dst = eidx;
    const int* src = eidx + EE;

    k_zero<<<1024, 256>>>();
    k_hist<<<400, 256>>>(dst);
    k_scan<<<1, 1024>>>();
    k_place<<<400, 256>>>(dst);

    k_h<<<NN / 8, 256>>>(x, W1);
    k_bsplit<<<1024, 256>>>(Wsc);
    k_w3split<<<72, 256>>>(Wm3);
    k_w2split<<<288, 256>>>(W2);

    const int sc_smem = (2 * 64 * ASTR + 2 * 32 * BSTR) * 2 + 256;
    cudaFuncSetAttribute(k_sc_mm, cudaFuncAttributeMaxDynamicSharedMemorySize, sc_smem);
    k_sc_mm<<<(NN + 63) / 64, 256, sc_smem>>>(x, attrs, out);

    cudaFuncSetAttribute(k_edge, cudaFuncAttributeMaxDynamicSharedMemorySize, EDGE_SMEM);
    k_edge<<<152, 288, EDGE_SMEM>>>(ee, sh, dst, src, Wm1, Wm2);

    cudaFuncSetAttribute(k_final_mm, cudaFuncAttributeMaxDynamicSharedMemorySize, sc_smem);
    k_final_mm<<<(NN + 63) / 64, 256, sc_smem>>>(out);
}

// round 11
// speedup vs baseline: 1.2412x; 1.1556x over previous
#include <cuda_runtime.h>
#include <cuda_bf16.h>
#include <mma.h>
#include <cstdint>

using namespace nvcuda;

#define NN   25000
#define EE   400000
#define FIN  256
#define CC   32
#define AA   9
#define WN   288     // CC*AA
#define BB   8
#define HH   64
#define SSP  4
#define FOUT 256
#define NTILE (EE / 64)   // 6250

__device__ float g_h[NN * CC];      // 3.2 MB
__device__ float g_agg[NN * WN];    // 28.8 MB
__device__ int   g_cnt[NN];
__device__ int   g_perm[EE];
// dst-sorted copies of edge inputs (coalesced k_edge loads)
__device__ float g_ee2[EE * BB];    // 12.8 MB
__device__ float g_sh2[EE * AA];    // 14.4 MB
__device__ int   g_dst2[EE];
__device__ int   g_src2[EE];
// pre-split Wsc [1024][256] bf16 hi/lo
__device__ __nv_bfloat16 g_Bhi[1024 * 256];
__device__ __nv_bfloat16 g_Blo[1024 * 256];
// pre-split W2 [288][256] bf16 hi/lo
__device__ __nv_bfloat16 g_W2hi[288 * 256];
__device__ __nv_bfloat16 g_W2lo[288 * 256];

__device__ __forceinline__ float silu_f(float v) {
    return v / (1.0f + __expf(-v));
}

// ---- packed f32x2 helpers ----
__device__ __forceinline__ void fma2(unsigned long long& acc, unsigned long long a,
                                     unsigned long long b) {
    asm("fma.rn.f32x2 %0, %1, %2, %0;" : "+l"(acc) : "l"(a), "l"(b));
}
__device__ __forceinline__ unsigned long long pack2(float x, float y) {
    unsigned long long r;
    asm("mov.b64 %0, {%1, %2};" : "=l"(r) : "f"(x), "f"(y));
    return r;
}
__device__ __forceinline__ float2 unpack2(unsigned long long v) {
    float2 r;
    asm("mov.b64 {%0, %1}, %2;" : "=f"(r.x), "=f"(r.y) : "l"(v));
    return r;
}
__device__ __forceinline__ unsigned long long lds64(const float* p) {
    return *reinterpret_cast<const unsigned long long*>(p);
}

// ---------------------------------------------------------------------------
__global__ void k_zero() {
    int i = blockIdx.x * blockDim.x + threadIdx.x;
    int stride = gridDim.x * blockDim.x;
    float4* p = (float4*)g_agg;
    const int n4 = (NN * WN) / 4;
    float4 z = make_float4(0.f, 0.f, 0.f, 0.f);
    for (int k = i; k < n4; k += stride) p[k] = z;
    for (int k = i; k < NN; k += stride) g_cnt[k] = 0;
}

// ---------------------------------------------------------------------------
// counting sort by dst
// ---------------------------------------------------------------------------
__global__ void k_hist(const int* __restrict__ dstG) {
    int i = blockIdx.x * blockDim.x + threadIdx.x;
    int stride = gridDim.x * blockDim.x;
    for (int e = i; e < EE; e += stride) atomicAdd(&g_cnt[dstG[e]], 1);
}

__global__ void __launch_bounds__(1024) k_scan() {
    __shared__ int smv[1024];
    const int CH = 25;
    int t = threadIdx.x;
    int base = t * CH;
    int v[CH];
    int s = 0;
#pragma unroll
    for (int i = 0; i < CH; i++) {
        int idx = base + i;
        v[i] = (idx < NN) ? g_cnt[idx] : 0;
        s += v[i];
    }
    smv[t] = s;
    __syncthreads();
    for (int off = 1; off < 1024; off <<= 1) {
        int x = (t >= off) ? smv[t - off] : 0;
        __syncthreads();
        smv[t] += x;
        __syncthreads();
    }
    int ex = (t > 0) ? smv[t - 1] : 0;
#pragma unroll
    for (int i = 0; i < CH; i++) {
        int idx = base + i;
        if (idx < NN) g_cnt[idx] = ex;
        ex += v[i];
    }
}

__global__ void k_place(const int* __restrict__ dstG) {
    int i = blockIdx.x * blockDim.x + threadIdx.x;
    int stride = gridDim.x * blockDim.x;
    for (int e = i; e < EE; e += stride) {
        int pos = atomicAdd(&g_cnt[dstG[e]], 1);
        g_perm[pos] = e;
    }
}

// permute edge inputs into sorted order (coalesced writes)
__global__ void k_permute(const float* __restrict__ ee, const float* __restrict__ sh,
                          const int* __restrict__ dst, const int* __restrict__ src) {
    int i = blockIdx.x * blockDim.x + threadIdx.x;
    int stride = gridDim.x * blockDim.x;
    for (int p = i; p < EE; p += stride) {
        int eg = g_perm[p];
        g_dst2[p] = dst[eg];
        g_src2[p] = src[eg];
    }
    for (int k = i; k < EE * BB; k += stride) {
        int p = k >> 3;
        g_ee2[k] = ee[(long long)g_perm[p] * BB + (k & 7)];
    }
    for (int k = i; k < EE * AA; k += stride) {
        int p = k / AA;
        g_sh2[k] = sh[(long long)g_perm[p] * AA + (k - AA * p)];
    }
}

// ---------------------------------------------------------------------------
// h = 0.25 * (x @ W1)    [NN, CC]
// ---------------------------------------------------------------------------
__global__ void __launch_bounds__(256) k_h(const float* __restrict__ x,
                                           const float* __restrict__ W1) {
    __shared__ float sW1[FIN * CC];
    __shared__ float sX[8][FIN];
    int t = threadIdx.x;
    int n0 = blockIdx.x * 8;
    for (int i = t; i < FIN * CC; i += 256) sW1[i] = W1[i];
    for (int i = t; i < 8 * FIN; i += 256)
        sX[i >> 8][i & 255] = x[(n0 + (i >> 8)) * FIN + (i & 255)];
    __syncthreads();
    int ty = t >> 5, tx = t & 31;
    float acc = 0.f;
#pragma unroll 8
    for (int f = 0; f < FIN; f++) acc += sX[ty][f] * sW1[f * CC + tx];
    g_h[(n0 + ty) * CC + tx] = 0.25f * acc;
}

// ---------------------------------------------------------------------------
// weight splits
// ---------------------------------------------------------------------------
__global__ void k_bsplit(const float* __restrict__ Wsc) {
    int idx = blockIdx.x * blockDim.x + threadIdx.x;
    if (idx >= 1024 * 256) return;
    float v = Wsc[idx];
    __nv_bfloat16 hi = __float2bfloat16(v);
    g_Bhi[idx] = hi;
    g_Blo[idx] = __float2bfloat16(v - __bfloat162float(hi));
}

__global__ void k_w2split(const float* __restrict__ W2) {
    int idx = blockIdx.x * blockDim.x + threadIdx.x;
    if (idx >= 288 * 256) return;
    float v = W2[idx];
    __nv_bfloat16 hi = __float2bfloat16(v);
    g_W2hi[idx] = hi;
    g_W2lo[idx] = __float2bfloat16(v - __bfloat162float(hi));
}

// ---------------------------------------------------------------------------
// tensor-core k_sc (R8, proven): out = xa @ Wsc, bf16 split
// ---------------------------------------------------------------------------
#define ASTR 40
#define BSTR 264

__global__ void __launch_bounds__(256) k_sc_mm(const float* __restrict__ x,
                                               const float* __restrict__ attrs,
                                               float* __restrict__ out) {
    extern __shared__ char smem[];
    __nv_bfloat16* sAhi = (__nv_bfloat16*)smem;
    __nv_bfloat16* sAlo = sAhi + 64 * ASTR;
    __nv_bfloat16* sBhi = sAlo + 64 * ASTR;
    __nv_bfloat16* sBlo = sBhi + 32 * BSTR;
    float* sOut = (float*)smem;

    int t = threadIdx.x;
    int wid = t >> 5;
    int warp_m = wid >> 2;
    int warp_n = wid & 3;
    int n0 = blockIdx.x * 64;

    wmma::fragment<wmma::accumulator, 16, 16, 16, float> acc[2][4];
#pragma unroll
    for (int im = 0; im < 2; im++)
#pragma unroll
        for (int jn = 0; jn < 4; jn++) wmma::fill_fragment(acc[im][jn], 0.0f);

    for (int kc = 0; kc < FIN * SSP; kc += 32) {
        for (int i = t; i < 64 * 32; i += 256) {
            int n = i >> 5, kk = i & 31;
            int k = kc + kk;
            int nn = n0 + n;
            float a = 0.f;
            if (nn < NN) a = x[nn * FIN + (k >> 2)] * attrs[nn * SSP + (k & 3)];
            __nv_bfloat16 hi = __float2bfloat16(a);
            sAhi[n * ASTR + kk] = hi;
            sAlo[n * ASTR + kk] = __float2bfloat16(a - __bfloat162float(hi));
        }
        for (int i = t; i < 32 * 256; i += 256) {
            int r = i >> 8, c = i & 255;
            sBhi[r * BSTR + c] = g_Bhi[(kc + r) * 256 + c];
            sBlo[r * BSTR + c] = g_Blo[(kc + r) * 256 + c];
        }
        __syncthreads();

#pragma unroll
        for (int kf = 0; kf < 2; kf++) {
            wmma::fragment<wmma::matrix_a, 16, 16, 16, __nv_bfloat16,
                           wmma::row_major> ahi[2], alo[2];
#pragma unroll
            for (int im = 0; im < 2; im++) {
                wmma::load_matrix_sync(ahi[im],
                    sAhi + (warp_m * 32 + 16 * im) * ASTR + kf * 16, ASTR);
                wmma::load_matrix_sync(alo[im],
                    sAlo + (warp_m * 32 + 16 * im) * ASTR + kf * 16, ASTR);
            }
#pragma unroll
            for (int jn = 0; jn < 4; jn++) {
                wmma::fragment<wmma::matrix_b, 16, 16, 16, __nv_bfloat16,
                               wmma::row_major> bhi, blo;
                wmma::load_matrix_sync(bhi,
                    sBhi + (kf * 16) * BSTR + warp_n * 64 + 16 * jn, BSTR);
                wmma::load_matrix_sync(blo,
                    sBlo + (kf * 16) * BSTR + warp_n * 64 + 16 * jn, BSTR);
#pragma unroll
                for (int im = 0; im < 2; im++) {
                    wmma::mma_sync(acc[im][jn], ahi[im], bhi, acc[im][jn]);
                    wmma::mma_sync(acc[im][jn], ahi[im], blo, acc[im][jn]);
                    wmma::mma_sync(acc[im][jn], alo[im], bhi, acc[im][jn]);
                }
            }
        }
        __syncthreads();
    }

    for (int half = 0; half < 2; half++) {
        if (warp_m == half) {
#pragma unroll
            for (int im = 0; im < 2; im++)
#pragma unroll
                for (int jn = 0; jn < 4; jn++)
                    wmma::store_matrix_sync(
                        sOut + (16 * im) * BSTR + warp_n * 64 + 16 * jn,
                        acc[im][jn], BSTR, wmma::mem_row_major);
        }
        __syncthreads();
        for (int i = t; i < 32 * 256; i += 256) {
            int r = i >> 8, c = i & 255;
            int nn = n0 + half * 32 + r;
            if (nn < NN) out[(long long)nn * FOUT + c] = sOut[r * BSTR + c];
        }
        __syncthreads();
    }
}

// ---------------------------------------------------------------------------
// fused edge kernel (R8 core, inputs pre-sorted: fully coalesced loads)
// ---------------------------------------------------------------------------
#define ACTP 65
#define TSTR 66

__global__ void __launch_bounds__(256, 1) k_edge(
    const float* __restrict__ Wm1, const float* __restrict__ Wm2,
    const float* __restrict__ Wm3) {
    extern __shared__ float sm[];
    float* sWm1  = sm;
    float* sWm2  = sWm1 + 512;
    float* sWm3  = sWm2 + 4096;
    float* sAct  = sWm3 + 18432;
    float* sActT = sAct + 64 * ACTP;
    float* sEE   = sActT + 64 * TSTR;
    float* sSH   = sEE + 512;
    float* sHs   = sSH + 576;
    int*   sDst  = (int*)(sHs + 2048);
    int*   sSrc  = sDst + 64;

    int t = threadIdx.x;
    for (int i = t; i < 512;   i += 256) sWm1[i] = Wm1[i];
    for (int i = t; i < 4096;  i += 256) sWm2[i] = Wm2[i];
    for (int i = t; i < 18432; i += 256) sWm3[i] = Wm3[i];
    __syncthreads();

    const int tx = t & 31, ty = t >> 5;
    const int e_loc = t & 63;
    const int j0 = (t >> 6) * 16;

    int cj[9], aj[9];
#pragma unroll
    for (int j = 0; j < 9; j++) {
        int o = tx + 32 * j;
        cj[j] = o / 9;
        aj[j] = o - 9 * cj[j];
    }

    for (int tile = blockIdx.x; tile < NTILE; tile += gridDim.x) {
        int e0g = tile * 64;
        if (t < 64) {
            sDst[t] = g_dst2[e0g + t];
            sSrc[t] = g_src2[e0g + t];
        }
        __syncthreads();
        for (int i = t; i < 64 * BB; i += 256) sEE[i] = g_ee2[(long long)e0g * BB + i];
        for (int i = t; i < 64 * AA; i += 256) sSH[i] = g_sh2[(long long)e0g * AA + i];
        for (int i = t; i < 64 * CC; i += 256) {
            int e = i >> 5, c = i & 31;
            sHs[i] = g_h[sSrc[e] * CC + c];
        }
        __syncthreads();

        // phase 1
        {
            float acc[16];
#pragma unroll
            for (int j = 0; j < 16; j++) acc[j] = 0.f;
#pragma unroll
            for (int b = 0; b < BB; b++) {
                float v = sEE[e_loc * BB + b];
#pragma unroll
                for (int j = 0; j < 16; j++) acc[j] += v * sWm1[b * HH + j0 + j];
            }
#pragma unroll
            for (int j = 0; j < 16; j++) sAct[e_loc * ACTP + j0 + j] = silu_f(acc[j]);
        }
        __syncthreads();

        // phase 2 (transposed output)
        {
            float acc[16];
#pragma unroll
            for (int j = 0; j < 16; j++) acc[j] = 0.f;
#pragma unroll 8
            for (int k = 0; k < HH; k++) {
                float v = sAct[e_loc * ACTP + k];
#pragma unroll
                for (int j = 0; j < 16; j++) acc[j] += v * sWm2[k * HH + j0 + j];
            }
#pragma unroll
            for (int j = 0; j < 16; j++)
                sActT[(j0 + j) * TSTR + e_loc] = silu_f(acc[j]);
        }
        __syncthreads();

        // phase 3: edge-pair FFMA2 + run-length scatter
        {
            unsigned long long acc2[4][9];
#pragma unroll
            for (int m = 0; m < 4; m++)
#pragma unroll
                for (int j = 0; j < 9; j++) acc2[m][j] = 0ull;

#pragma unroll 2
            for (int k = 0; k < HH; k++) {
                unsigned long long a2[4];
#pragma unroll
                for (int m = 0; m < 4; m++)
                    a2[m] = lds64(&sActT[k * TSTR + 8 * ty + 2 * m]);
#pragma unroll
                for (int j = 0; j < 9; j++) {
                    float b = sWm3[k * WN + tx + 32 * j];
                    unsigned long long bb = pack2(b, b);
#pragma unroll
                    for (int m = 0; m < 4; m++) fma2(acc2[m][j], a2[m], bb);
                }
            }

            float racc[9];
#pragma unroll
            for (int j = 0; j < 9; j++) racc[j] = 0.f;
            int cur = sDst[8 * ty];

#pragma unroll
            for (int m = 0; m < 4; m++) {
                int e0 = 8 * ty + 2 * m;
                int e1 = e0 + 1;
                const float* hs0 = &sHs[e0 * CC];
                const float* hs1 = &sHs[e1 * CC];
                const float* sh0 = &sSH[e0 * AA];
                const float* sh1 = &sSH[e1 * AA];
                int d0 = sDst[e0], d1 = sDst[e1];
                if (d0 != cur) {
                    float* dp = g_agg + (long long)cur * WN;
#pragma unroll
                    for (int j = 0; j < 9; j++) {
                        atomicAdd(dp + tx + 32 * j, racc[j]);
                        racc[j] = 0.f;
                    }
                    cur = d0;
                }
#pragma unroll
                for (int j = 0; j < 9; j++) {
                    float2 w = unpack2(acc2[m][j]);
                    racc[j] += w.x * hs0[cj[j]] * sh0[aj[j]];
                }
                if (d1 != cur) {
                    float* dp = g_agg + (long long)cur * WN;
#pragma unroll
                    for (int j = 0; j < 9; j++) {
                        atomicAdd(dp + tx + 32 * j, racc[j]);
                        racc[j] = 0.f;
                    }
                    cur = d1;
                }
#pragma unroll
                for (int j = 0; j < 9; j++) {
                    float2 w = unpack2(acc2[m][j]);
                    racc[j] += w.y * hs1[cj[j]] * sh1[aj[j]];
                }
            }
            {
                float* dp = g_agg + (long long)cur * WN;
#pragma unroll
                for (int j = 0; j < 9; j++) atomicAdd(dp + tx + 32 * j, racc[j]);
            }
        }
        __syncthreads();
    }
}

// ---------------------------------------------------------------------------
// k_final_mm: out = silu(agg @ W2) + out, wmma bf16 split, K=288
// ---------------------------------------------------------------------------
__global__ void __launch_bounds__(256) k_final_mm(float* __restrict__ out) {
    extern __shared__ char smem[];
    __nv_bfloat16* sAhi = (__nv_bfloat16*)smem;
    __nv_bfloat16* sAlo = sAhi + 64 * ASTR;
    __nv_bfloat16* sBhi = sAlo + 64 * ASTR;
    __nv_bfloat16* sBlo = sBhi + 32 * BSTR;
    float* sOut = (float*)smem;

    int t = threadIdx.x;
    int wid = t >> 5;
    int warp_m = wid >> 2;
    int warp_n = wid & 3;
    int n0 = blockIdx.x * 64;

    wmma::fragment<wmma::accumulator, 16, 16, 16, float> acc[2][4];
#pragma unroll
    for (int im = 0; im < 2; im++)
#pragma unroll
        for (int jn = 0; jn < 4; jn++) wmma::fill_fragment(acc[im][jn], 0.0f);

    for (int kc = 0; kc < WN; kc += 32) {
        for (int i = t; i < 64 * 32; i += 256) {
            int n = i >> 5, kk = i & 31;
            int nn = n0 + n;
            float a = 0.f;
            if (nn < NN) a = g_agg[(long long)nn * WN + kc + kk];
            __nv_bfloat16 hi = __float2bfloat16(a);
            sAhi[n * ASTR + kk] = hi;
            sAlo[n * ASTR + kk] = __float2bfloat16(a - __bfloat162float(hi));
        }
        for (int i = t; i < 32 * 256; i += 256) {
            int r = i >> 8, c = i & 255;
            sBhi[r * BSTR + c] = g_W2hi[(kc + r) * 256 + c];
            sBlo[r * BSTR + c] = g_W2lo[(kc + r) * 256 + c];
        }
        __syncthreads();

#pragma unroll
        for (int kf = 0; kf < 2; kf++) {
            wmma::fragment<wmma::matrix_a, 16, 16, 16, __nv_bfloat16,
                           wmma::row_major> ahi[2], alo[2];
#pragma unroll
            for (int im = 0; im < 2; im++) {
                wmma::load_matrix_sync(ahi[im],
                    sAhi + (warp_m * 32 + 16 * im) * ASTR + kf * 16, ASTR);
                wmma::load_matrix_sync(alo[im],
                    sAlo + (warp_m * 32 + 16 * im) * ASTR + kf * 16, ASTR);
            }
#pragma unroll
            for (int jn = 0; jn < 4; jn++) {
                wmma::fragment<wmma::matrix_b, 16, 16, 16, __nv_bfloat16,
                               wmma::row_major> bhi, blo;
                wmma::load_matrix_sync(bhi,
                    sBhi + (kf * 16) * BSTR + warp_n * 64 + 16 * jn, BSTR);
                wmma::load_matrix_sync(blo,
                    sBlo + (kf * 16) * BSTR + warp_n * 64 + 16 * jn, BSTR);
#pragma unroll
                for (int im = 0; im < 2; im++) {
                    wmma::mma_sync(acc[im][jn], ahi[im], bhi, acc[im][jn]);
                    wmma::mma_sync(acc[im][jn], ahi[im], blo, acc[im][jn]);
                    wmma::mma_sync(acc[im][jn], alo[im], bhi, acc[im][jn]);
                }
            }
        }
        __syncthreads();
    }

    for (int half = 0; half < 2; half++) {
        if (warp_m == half) {
#pragma unroll
            for (int im = 0; im < 2; im++)
#pragma unroll
                for (int jn = 0; jn < 4; jn++)
                    wmma::store_matrix_sync(
                        sOut + (16 * im) * BSTR + warp_n * 64 + 16 * jn,
                        acc[im][jn], BSTR, wmma::mem_row_major);
        }
        __syncthreads();
        for (int i = t; i < 32 * 256; i += 256) {
            int r = i >> 8, c = i & 255;
            int nn = n0 + half * 32 + r;
            if (nn < NN) {
                long long o = (long long)nn * FOUT + c;
                out[o] = silu_f(sOut[r * BSTR + c]) + out[o];
            }
        }
        __syncthreads();
    }
}

// ---------------------------------------------------------------------------
extern "C" void kernel_launch(void* const* d_in, const int* in_sizes, int n_in,
                              void* d_out, int out_size) {
    const float* x     = (const float*)d_in[0];
    const float* attrs = (const float*)d_in[1];
    const float* ee    = (const float*)d_in[2];
    const float* sh    = (const float*)d_in[3];
    const int*   eidx  = (const int*)d_in[4];
    const float* W1    = (const float*)d_in[5];
    const float* Wm1   = (const float*)d_in[6];
    const float* Wm2   = (const float*)d_in[7];
    const float* Wm3   = (const float*)d_in[8];
    const float* W2    = (const float*)d_in[9];
    const float* Wsc   = (const float*)d_in[10];
    float* out = (float*)d_out;

    const int* dst = eidx;
    const int* src = eidx + EE;

    k_zero<<<1024, 256>>>();
    k_hist<<<400, 256>>>(dst);
    k_scan<<<1, 1024>>>();
    k_place<<<400, 256>>>(dst);
    k_permute<<<592, 256>>>(ee, sh, dst, src);

    k_h<<<NN / 8, 256>>>(x, W1);
    k_bsplit<<<1024, 256>>>(Wsc);
    k_w2split<<<288, 256>>>(W2);

    const int sc_smem = (2 * 64 * ASTR + 2 * 32 * BSTR) * 2 + 256;
    cudaFuncSetAttribute(k_sc_mm, cudaFuncAttributeMaxDynamicSharedMemorySize, sc_smem);
    k_sc_mm<<<(NN + 63) / 64, 256, sc_smem>>>(x, attrs, out);

    const int edge_smem =
        (512 + 4096 + 18432 + 64 * ACTP + 64 * TSTR + 512 + 576 + 2048) * 4 +
        2 * 64 * 4 + 256;
    cudaFuncSetAttribute(k_edge, cudaFuncAttributeMaxDynamicSharedMemorySize, edge_smem);
    k_edge<<<152, 256, edge_smem>>>(Wm1, Wm2, Wm3);

    cudaFuncSetAttribute(k_final_mm, cudaFuncAttributeMaxDynamicSharedMemorySize, sc_smem);
    k_final_mm<<<(NN + 63) / 64, 256, sc_smem>>>(out);
}

// round 12
// speedup vs baseline: 1.2483x; 1.0058x over previous
#include <cuda_runtime.h>
#include <cuda_bf16.h>
#include <mma.h>
#include <cstdint>

using namespace nvcuda;

#define NN   25000
#define EE   400000
#define FIN  256
#define CC   32
#define AA   9
#define WN   288     // CC*AA
#define BB   8
#define HH   64
#define SSP  4
#define FOUT 256

__device__ float g_h[NN * CC];      // 3.2 MB
__device__ float g_agg[NN * WN];    // 28.8 MB
__device__ int   g_cnt[NN];
__device__ int   g_perm[EE];
// pre-split Wsc [1024][256] bf16 hi/lo
__device__ __nv_bfloat16 g_Bhi[1024 * 256];
__device__ __nv_bfloat16 g_Blo[1024 * 256];
// pre-split W2 [288][256] bf16 hi/lo
__device__ __nv_bfloat16 g_W2hi[288 * 256];
__device__ __nv_bfloat16 g_W2lo[288 * 256];

__device__ __forceinline__ float silu_f(float v) {
    return v / (1.0f + __expf(-v));
}

// ---- packed f32x2 helpers ----
__device__ __forceinline__ void fma2(unsigned long long& acc, unsigned long long a,
                                     unsigned long long b) {
    asm("fma.rn.f32x2 %0, %1, %2, %0;" : "+l"(acc) : "l"(a), "l"(b));
}
__device__ __forceinline__ unsigned long long pack2(float x, float y) {
    unsigned long long r;
    asm("mov.b64 %0, {%1, %2};" : "=l"(r) : "f"(x), "f"(y));
    return r;
}
__device__ __forceinline__ float2 unpack2(unsigned long long v) {
    float2 r;
    asm("mov.b64 {%0, %1}, %2;" : "=f"(r.x), "=f"(r.y) : "l"(v));
    return r;
}
__device__ __forceinline__ unsigned long long lds64(const float* p) {
    return *reinterpret_cast<const unsigned long long*>(p);
}

// ---------------------------------------------------------------------------
__global__ void k_zero() {
    int i = blockIdx.x * blockDim.x + threadIdx.x;
    int stride = gridDim.x * blockDim.x;
    float4* p = (float4*)g_agg;
    const int n4 = (NN * WN) / 4;
    float4 z = make_float4(0.f, 0.f, 0.f, 0.f);
    for (int k = i; k < n4; k += stride) p[k] = z;
    for (int k = i; k < NN; k += stride) g_cnt[k] = 0;
}

// ---------------------------------------------------------------------------
// counting sort by dst
// ---------------------------------------------------------------------------
__global__ void k_hist(const int* __restrict__ dstG) {
    int i = blockIdx.x * blockDim.x + threadIdx.x;
    int stride = gridDim.x * blockDim.x;
    for (int e = i; e < EE; e += stride) atomicAdd(&g_cnt[dstG[e]], 1);
}

__global__ void __launch_bounds__(1024) k_scan() {
    __shared__ int smv[1024];
    const int CH = 25;
    int t = threadIdx.x;
    int base = t * CH;
    int v[CH];
    int s = 0;
#pragma unroll
    for (int i = 0; i < CH; i++) {
        int idx = base + i;
        v[i] = (idx < NN) ? g_cnt[idx] : 0;
        s += v[i];
    }
    smv[t] = s;
    __syncthreads();
    for (int off = 1; off < 1024; off <<= 1) {
        int x = (t >= off) ? smv[t - off] : 0;
        __syncthreads();
        smv[t] += x;
        __syncthreads();
    }
    int ex = (t > 0) ? smv[t - 1] : 0;
#pragma unroll
    for (int i = 0; i < CH; i++) {
        int idx = base + i;
        if (idx < NN) g_cnt[idx] = ex;
        ex += v[i];
    }
}

__global__ void k_place(const int* __restrict__ dstG) {
    int i = blockIdx.x * blockDim.x + threadIdx.x;
    int stride = gridDim.x * blockDim.x;
    for (int e = i; e < EE; e += stride) {
        int pos = atomicAdd(&g_cnt[dstG[e]], 1);
        g_perm[pos] = e;
    }
}

// ---------------------------------------------------------------------------
// h = 0.25 * (x @ W1)    [NN, CC]
// ---------------------------------------------------------------------------
__global__ void __launch_bounds__(256) k_h(const float* __restrict__ x,
                                           const float* __restrict__ W1) {
    __shared__ float sW1[FIN * CC];
    __shared__ float sX[8][FIN];
    int t = threadIdx.x;
    int n0 = blockIdx.x * 8;
    for (int i = t; i < FIN * CC; i += 256) sW1[i] = W1[i];
    for (int i = t; i < 8 * FIN; i += 256)
        sX[i >> 8][i & 255] = x[(n0 + (i >> 8)) * FIN + (i & 255)];
    __syncthreads();
    int ty = t >> 5, tx = t & 31;
    float acc = 0.f;
#pragma unroll 8
    for (int f = 0; f < FIN; f++) acc += sX[ty][f] * sW1[f * CC + tx];
    g_h[(n0 + ty) * CC + tx] = 0.25f * acc;
}

// ---------------------------------------------------------------------------
// weight splits
// ---------------------------------------------------------------------------
__global__ void k_bsplit(const float* __restrict__ Wsc) {
    int idx = blockIdx.x * blockDim.x + threadIdx.x;
    if (idx >= 1024 * 256) return;
    float v = Wsc[idx];
    __nv_bfloat16 hi = __float2bfloat16(v);
    g_Bhi[idx] = hi;
    g_Blo[idx] = __float2bfloat16(v - __bfloat162float(hi));
}

__global__ void k_w2split(const float* __restrict__ W2) {
    int idx = blockIdx.x * blockDim.x + threadIdx.x;
    if (idx >= 288 * 256) return;
    float v = W2[idx];
    __nv_bfloat16 hi = __float2bfloat16(v);
    g_W2hi[idx] = hi;
    g_W2lo[idx] = __float2bfloat16(v - __bfloat162float(hi));
}

// ---------------------------------------------------------------------------
// tensor-core k_sc (R8, proven): out = xa @ Wsc, bf16 split
// ---------------------------------------------------------------------------
#define ASTR 40
#define BSTR 264

__global__ void __launch_bounds__(256) k_sc_mm(const float* __restrict__ x,
                                               const float* __restrict__ attrs,
                                               float* __restrict__ out) {
    extern __shared__ char smem[];
    __nv_bfloat16* sAhi = (__nv_bfloat16*)smem;
    __nv_bfloat16* sAlo = sAhi + 64 * ASTR;
    __nv_bfloat16* sBhi = sAlo + 64 * ASTR;
    __nv_bfloat16* sBlo = sBhi + 32 * BSTR;
    float* sOut = (float*)smem;

    int t = threadIdx.x;
    int wid = t >> 5;
    int warp_m = wid >> 2;
    int warp_n = wid & 3;
    int n0 = blockIdx.x * 64;

    wmma::fragment<wmma::accumulator, 16, 16, 16, float> acc[2][4];
#pragma unroll
    for (int im = 0; im < 2; im++)
#pragma unroll
        for (int jn = 0; jn < 4; jn++) wmma::fill_fragment(acc[im][jn], 0.0f);

    for (int kc = 0; kc < FIN * SSP; kc += 32) {
        for (int i = t; i < 64 * 32; i += 256) {
            int n = i >> 5, kk = i & 31;
            int k = kc + kk;
            int nn = n0 + n;
            float a = 0.f;
            if (nn < NN) a = x[nn * FIN + (k >> 2)] * attrs[nn * SSP + (k & 3)];
            __nv_bfloat16 hi = __float2bfloat16(a);
            sAhi[n * ASTR + kk] = hi;
            sAlo[n * ASTR + kk] = __float2bfloat16(a - __bfloat162float(hi));
        }
        for (int i = t; i < 32 * 256; i += 256) {
            int r = i >> 8, c = i & 255;
            sBhi[r * BSTR + c] = g_Bhi[(kc + r) * 256 + c];
            sBlo[r * BSTR + c] = g_Blo[(kc + r) * 256 + c];
        }
        __syncthreads();

#pragma unroll
        for (int kf = 0; kf < 2; kf++) {
            wmma::fragment<wmma::matrix_a, 16, 16, 16, __nv_bfloat16,
                           wmma::row_major> ahi[2], alo[2];
#pragma unroll
            for (int im = 0; im < 2; im++) {
                wmma::load_matrix_sync(ahi[im],
                    sAhi + (warp_m * 32 + 16 * im) * ASTR + kf * 16, ASTR);
                wmma::load_matrix_sync(alo[im],
                    sAlo + (warp_m * 32 + 16 * im) * ASTR + kf * 16, ASTR);
            }
#pragma unroll
            for (int jn = 0; jn < 4; jn++) {
                wmma::fragment<wmma::matrix_b, 16, 16, 16, __nv_bfloat16,
                               wmma::row_major> bhi, blo;
                wmma::load_matrix_sync(bhi,
                    sBhi + (kf * 16) * BSTR + warp_n * 64 + 16 * jn, BSTR);
                wmma::load_matrix_sync(blo,
                    sBlo + (kf * 16) * BSTR + warp_n * 64 + 16 * jn, BSTR);
#pragma unroll
                for (int im = 0; im < 2; im++) {
                    wmma::mma_sync(acc[im][jn], ahi[im], bhi, acc[im][jn]);
                    wmma::mma_sync(acc[im][jn], ahi[im], blo, acc[im][jn]);
                    wmma::mma_sync(acc[im][jn], alo[im], bhi, acc[im][jn]);
                }
            }
        }
        __syncthreads();
    }

    for (int half = 0; half < 2; half++) {
        if (warp_m == half) {
#pragma unroll
            for (int im = 0; im < 2; im++)
#pragma unroll
                for (int jn = 0; jn < 4; jn++)
                    wmma::store_matrix_sync(
                        sOut + (16 * im) * BSTR + warp_n * 64 + 16 * jn,
                        acc[im][jn], BSTR, wmma::mem_row_major);
        }
        __syncthreads();
        for (int i = t; i < 32 * 256; i += 256) {
            int r = i >> 8, c = i & 255;
            int nn = n0 + half * 32 + r;
            if (nn < NN) out[(long long)nn * FOUT + c] = sOut[r * BSTR + c];
        }
        __syncthreads();
    }
}

// ---------------------------------------------------------------------------
// fused edge kernel (R8/R6 core: 256 threads, 64-edge tiles, perm gathers)
// ---------------------------------------------------------------------------
#define ACTP 65
#define TSTR 66

__global__ void __launch_bounds__(256, 1) k_edge(
    const float* __restrict__ eeG, const float* __restrict__ shG,
    const int* __restrict__ dstG, const int* __restrict__ srcG,
    const float* __restrict__ Wm1, const float* __restrict__ Wm2,
    const float* __restrict__ Wm3) {
    extern __shared__ float sm[];
    float* sWm1  = sm;
    float* sWm2  = sWm1 + 512;
    float* sWm3  = sWm2 + 4096;
    float* sAct  = sWm3 + 18432;
    float* sActT = sAct + 64 * ACTP;
    float* sEE   = sActT + 64 * TSTR;
    float* sSH   = sEE + 512;
    float* sHs   = sSH + 576;
    int*   sDst  = (int*)(sHs + 2048);
    int*   sSrc  = sDst + 64;
    int*   sEid  = sSrc + 64;

    int t = threadIdx.x;
    for (int i = t; i < 512;   i += 256) sWm1[i] = Wm1[i];
    for (int i = t; i < 4096;  i += 256) sWm2[i] = Wm2[i];
    for (int i = t; i < 18432; i += 256) sWm3[i] = Wm3[i];
    __syncthreads();

    const int tx = t & 31, ty = t >> 5;
    const int e_loc = t & 63;
    const int j0 = (t >> 6) * 16;

    int cj[9], aj[9];
#pragma unroll
    for (int j = 0; j < 9; j++) {
        int o = tx + 32 * j;
        cj[j] = o / 9;
        aj[j] = o - 9 * cj[j];
    }

    for (int tile = blockIdx.x; tile < EE / 64; tile += gridDim.x) {
        int e0g = tile * 64;
        if (t < 64) {
            int eg = g_perm[e0g + t];
            sEid[t] = eg;
            sDst[t] = dstG[eg];
            sSrc[t] = srcG[eg];
        }
        __syncthreads();
        for (int i = t; i < 64 * BB; i += 256) {
            int e = i >> 3, b = i & 7;
            sEE[i] = eeG[sEid[e] * BB + b];
        }
        for (int i = t; i < 64 * AA; i += 256) {
            int e = i / AA, a = i - AA * e;
            sSH[i] = shG[sEid[e] * AA + a];
        }
        for (int i = t; i < 64 * CC; i += 256) {
            int e = i >> 5, c = i & 31;
            sHs[i] = g_h[sSrc[e] * CC + c];
        }
        __syncthreads();

        // phase 1
        {
            float acc[16];
#pragma unroll
            for (int j = 0; j < 16; j++) acc[j] = 0.f;
#pragma unroll
            for (int b = 0; b < BB; b++) {
                float v = sEE[e_loc * BB + b];
#pragma unroll
                for (int j = 0; j < 16; j++) acc[j] += v * sWm1[b * HH + j0 + j];
            }
#pragma unroll
            for (int j = 0; j < 16; j++) sAct[e_loc * ACTP + j0 + j] = silu_f(acc[j]);
        }
        __syncthreads();

        // phase 2 (transposed output)
        {
            float acc[16];
#pragma unroll
            for (int j = 0; j < 16; j++) acc[j] = 0.f;
#pragma unroll 8
            for (int k = 0; k < HH; k++) {
                float v = sAct[e_loc * ACTP + k];
#pragma unroll
                for (int j = 0; j < 16; j++) acc[j] += v * sWm2[k * HH + j0 + j];
            }
#pragma unroll
            for (int j = 0; j < 16; j++)
                sActT[(j0 + j) * TSTR + e_loc] = silu_f(acc[j]);
        }
        __syncthreads();

        // phase 3: edge-pair FFMA2 + run-length scatter
        {
            unsigned long long acc2[4][9];
#pragma unroll
            for (int m = 0; m < 4; m++)
#pragma unroll
                for (int j = 0; j < 9; j++) acc2[m][j] = 0ull;

#pragma unroll 2
            for (int k = 0; k < HH; k++) {
                unsigned long long a2[4];
#pragma unroll
                for (int m = 0; m < 4; m++)
                    a2[m] = lds64(&sActT[k * TSTR + 8 * ty + 2 * m]);
#pragma unroll
                for (int j = 0; j < 9; j++) {
                    float b = sWm3[k * WN + tx + 32 * j];
                    unsigned long long bb = pack2(b, b);
#pragma unroll
                    for (int m = 0; m < 4; m++) fma2(acc2[m][j], a2[m], bb);
                }
            }

            float racc[9];
#pragma unroll
            for (int j = 0; j < 9; j++) racc[j] = 0.f;
            int cur = sDst[8 * ty];

#pragma unroll
            for (int m = 0; m < 4; m++) {
                int e0 = 8 * ty + 2 * m;
                int e1 = e0 + 1;
                const float* hs0 = &sHs[e0 * CC];
                const float* hs1 = &sHs[e1 * CC];
                const float* sh0 = &sSH[e0 * AA];
                const float* sh1 = &sSH[e1 * AA];
                int d0 = sDst[e0], d1 = sDst[e1];
                if (d0 != cur) {
                    float* dp = g_agg + (long long)cur * WN;
#pragma unroll
                    for (int j = 0; j < 9; j++) {
                        atomicAdd(dp + tx + 32 * j, racc[j]);
                        racc[j] = 0.f;
                    }
                    cur = d0;
                }
#pragma unroll
                for (int j = 0; j < 9; j++) {
                    float2 w = unpack2(acc2[m][j]);
                    racc[j] += w.x * hs0[cj[j]] * sh0[aj[j]];
                }
                if (d1 != cur) {
                    float* dp = g_agg + (long long)cur * WN;
#pragma unroll
                    for (int j = 0; j < 9; j++) {
                        atomicAdd(dp + tx + 32 * j, racc[j]);
                        racc[j] = 0.f;
                    }
                    cur = d1;
                }
#pragma unroll
                for (int j = 0; j < 9; j++) {
                    float2 w = unpack2(acc2[m][j]);
                    racc[j] += w.y * hs1[cj[j]] * sh1[aj[j]];
                }
            }
            {
                float* dp = g_agg + (long long)cur * WN;
#pragma unroll
                for (int j = 0; j < 9; j++) atomicAdd(dp + tx + 32 * j, racc[j]);
            }
        }
        __syncthreads();
    }
}

// ---------------------------------------------------------------------------
// k_final_mm: out = silu(agg @ W2) + out, wmma bf16 split, K=288
// ---------------------------------------------------------------------------
__global__ void __launch_bounds__(256) k_final_mm(float* __restrict__ out) {
    extern __shared__ char smem[];
    __nv_bfloat16* sAhi = (__nv_bfloat16*)smem;
    __nv_bfloat16* sAlo = sAhi + 64 * ASTR;
    __nv_bfloat16* sBhi = sAlo + 64 * ASTR;
    __nv_bfloat16* sBlo = sBhi + 32 * BSTR;
    float* sOut = (float*)smem;

    int t = threadIdx.x;
    int wid = t >> 5;
    int warp_m = wid >> 2;
    int warp_n = wid & 3;
    int n0 = blockIdx.x * 64;

    wmma::fragment<wmma::accumulator, 16, 16, 16, float> acc[2][4];
#pragma unroll
    for (int im = 0; im < 2; im++)
#pragma unroll
        for (int jn = 0; jn < 4; jn++) wmma::fill_fragment(acc[im][jn], 0.0f);

    for (int kc = 0; kc < WN; kc += 32) {
        for (int i = t; i < 64 * 32; i += 256) {
            int n = i >> 5, kk = i & 31;
            int nn = n0 + n;
            float a = 0.f;
            if (nn < NN) a = g_agg[(long long)nn * WN + kc + kk];
            __nv_bfloat16 hi = __float2bfloat16(a);
            sAhi[n * ASTR + kk] = hi;
            sAlo[n * ASTR + kk] = __float2bfloat16(a - __bfloat162float(hi));
        }
        for (int i = t; i < 32 * 256; i += 256) {
            int r = i >> 8, c = i & 255;
            sBhi[r * BSTR + c] = g_W2hi[(kc + r) * 256 + c];
            sBlo[r * BSTR + c] = g_W2lo[(kc + r) * 256 + c];
        }
        __syncthreads();

#pragma unroll
        for (int kf = 0; kf < 2; kf++) {
            wmma::fragment<wmma::matrix_a, 16, 16, 16, __nv_bfloat16,
                           wmma::row_major> ahi[2], alo[2];
#pragma unroll
            for (int im = 0; im < 2; im++) {
                wmma::load_matrix_sync(ahi[im],
                    sAhi + (warp_m * 32 + 16 * im) * ASTR + kf * 16, ASTR);
                wmma::load_matrix_sync(alo[im],
                    sAlo + (warp_m * 32 + 16 * im) * ASTR + kf * 16, ASTR);
            }
#pragma unroll
            for (int jn = 0; jn < 4; jn++) {
                wmma::fragment<wmma::matrix_b, 16, 16, 16, __nv_bfloat16,
                               wmma::row_major> bhi, blo;
                wmma::load_matrix_sync(bhi,
                    sBhi + (kf * 16) * BSTR + warp_n * 64 + 16 * jn, BSTR);
                wmma::load_matrix_sync(blo,
                    sBlo + (kf * 16) * BSTR + warp_n * 64 + 16 * jn, BSTR);
#pragma unroll
                for (int im = 0; im < 2; im++) {
                    wmma::mma_sync(acc[im][jn], ahi[im], bhi, acc[im][jn]);
                    wmma::mma_sync(acc[im][jn], ahi[im], blo, acc[im][jn]);
                    wmma::mma_sync(acc[im][jn], alo[im], bhi, acc[im][jn]);
                }
            }
        }
        __syncthreads();
    }

    for (int half = 0; half < 2; half++) {
        if (warp_m == half) {
#pragma unroll
            for (int im = 0; im < 2; im++)
#pragma unroll
                for (int jn = 0; jn < 4; jn++)
                    wmma::store_matrix_sync(
                        sOut + (16 * im) * BSTR + warp_n * 64 + 16 * jn,
                        acc[im][jn], BSTR, wmma::mem_row_major);
        }
        __syncthreads();
        for (int i = t; i < 32 * 256; i += 256) {
            int r = i >> 8, c = i & 255;
            int nn = n0 + half * 32 + r;
            if (nn < NN) {
                long long o = (long long)nn * FOUT + c;
                out[o] = silu_f(sOut[r * BSTR + c]) + out[o];
            }
        }
        __syncthreads();
    }
}

// ---------------------------------------------------------------------------
extern "C" void kernel_launch(void* const* d_in, const int* in_sizes, int n_in,
                              void* d_out, int out_size) {
    const float* x     = (const float*)d_in[0];
    const float* attrs = (const float*)d_in[1];
    const float* ee    = (const float*)d_in[2];
    const float* sh    = (const float*)d_in[3];
    const int*   eidx  = (const int*)d_in[4];
    const float* W1    = (const float*)d_in[5];
    const float* Wm1   = (const float*)d_in[6];
    const float* Wm2   = (const float*)d_in[7];
    const float* Wm3   = (const float*)d_in[8];
    const float* W2    = (const float*)d_in[9];
    const float* Wsc   = (const float*)d_in[10];
    float* out = (float*)d_out;

    const int* dst = eidx;
    const int* src = eidx + EE;

    k_zero<<<1024, 256>>>();
    k_hist<<<400, 256>>>(dst);
    k_scan<<<1, 1024>>>();
    k_place<<<400, 256>>>(dst);

    k_h<<<NN / 8, 256>>>(x, W1);
    k_bsplit<<<1024, 256>>>(Wsc);
    k_w2split<<<288, 256>>>(W2);

    const int sc_smem = (2 * 64 * ASTR + 2 * 32 * BSTR) * 2 + 256;
    cudaFuncSetAttribute(k_sc_mm, cudaFuncAttributeMaxDynamicSharedMemorySize, sc_smem);
    k_sc_mm<<<(NN + 63) / 64, 256, sc_smem>>>(x, attrs, out);

    const int edge_smem =
        (512 + 4096 + 18432 + 64 * ACTP + 64 * TSTR + 512 + 576 + 2048) * 4 +
        3 * 64 * 4 + 256;
    cudaFuncSetAttribute(k_edge, cudaFuncAttributeMaxDynamicSharedMemorySize, edge_smem);
    k_edge<<<152, 256, edge_smem>>>(ee, sh, dst, src, Wm1, Wm2, Wm3);

    cudaFuncSetAttribute(k_final_mm, cudaFuncAttributeMaxDynamicSharedMemorySize, sc_smem);
    k_final_mm<<<(NN + 63) / 64, 256, sc_smem>>>(out);
}

// round 13
// speedup vs baseline: 1.4432x; 1.1561x over previous
#include <cuda_runtime.h>
#include <cuda_bf16.h>
#include <mma.h>
#include <cstdint>

using namespace nvcuda;

#define NN   25000
#define EE   400000
#define FIN  256
#define CC   32
#define AA   9
#define WN   288     // CC*AA
#define BB   8
#define HH   64
#define SSP  4
#define FOUT 256

__device__ float g_h[NN * CC];      // 3.2 MB
__device__ float g_agg[NN * WN];    // 28.8 MB
__device__ int   g_cnt[NN];
__device__ int   g_perm[EE];
// pre-split Wsc [1024][256] bf16 hi/lo
__device__ __nv_bfloat16 g_Bhi[1024 * 256];
__device__ __nv_bfloat16 g_Blo[1024 * 256];

__device__ __forceinline__ float silu_f(float v) {
    return v / (1.0f + __expf(-v));
}

// ---- packed f32x2 helpers ----
__device__ __forceinline__ void fma2(unsigned long long& acc, unsigned long long a,
                                     unsigned long long b) {
    asm("fma.rn.f32x2 %0, %1, %2, %0;" : "+l"(acc) : "l"(a), "l"(b));
}
__device__ __forceinline__ unsigned long long pack2(float x, float y) {
    unsigned long long r;
    asm("mov.b64 %0, {%1, %2};" : "=l"(r) : "f"(x), "f"(y));
    return r;
}
__device__ __forceinline__ float2 unpack2(unsigned long long v) {
    float2 r;
    asm("mov.b64 {%0, %1}, %2;" : "=f"(r.x), "=f"(r.y) : "l"(v));
    return r;
}
__device__ __forceinline__ unsigned long long lds64(const float* p) {
    return *reinterpret_cast<const unsigned long long*>(p);
}

// ---------------------------------------------------------------------------
__global__ void k_zero() {
    int i = blockIdx.x * blockDim.x + threadIdx.x;
    int stride = gridDim.x * blockDim.x;
    float4* p = (float4*)g_agg;
    const int n4 = (NN * WN) / 4;
    float4 z = make_float4(0.f, 0.f, 0.f, 0.f);
    for (int k = i; k < n4; k += stride) p[k] = z;
    for (int k = i; k < NN; k += stride) g_cnt[k] = 0;
}

// ---------------------------------------------------------------------------
// counting sort by dst
// ---------------------------------------------------------------------------
__global__ void k_hist(const int* __restrict__ dstG) {
    int i = blockIdx.x * blockDim.x + threadIdx.x;
    int stride = gridDim.x * blockDim.x;
    for (int e = i; e < EE; e += stride) atomicAdd(&g_cnt[dstG[e]], 1);
}

__global__ void __launch_bounds__(1024) k_scan() {
    __shared__ int smv[1024];
    const int CH = 25;
    int t = threadIdx.x;
    int base = t * CH;
    int v[CH];
    int s = 0;
#pragma unroll
    for (int i = 0; i < CH; i++) {
        int idx = base + i;
        v[i] = (idx < NN) ? g_cnt[idx] : 0;
        s += v[i];
    }
    smv[t] = s;
    __syncthreads();
    for (int off = 1; off < 1024; off <<= 1) {
        int x = (t >= off) ? smv[t - off] : 0;
        __syncthreads();
        smv[t] += x;
        __syncthreads();
    }
    int ex = (t > 0) ? smv[t - 1] : 0;
#pragma unroll
    for (int i = 0; i < CH; i++) {
        int idx = base + i;
        if (idx < NN) g_cnt[idx] = ex;
        ex += v[i];
    }
}

__global__ void k_place(const int* __restrict__ dstG) {
    int i = blockIdx.x * blockDim.x + threadIdx.x;
    int stride = gridDim.x * blockDim.x;
    for (int e = i; e < EE; e += stride) {
        int pos = atomicAdd(&g_cnt[dstG[e]], 1);
        g_perm[pos] = e;
    }
}

// ---------------------------------------------------------------------------
// h = 0.25 * (x @ W1)    [NN, CC]
// ---------------------------------------------------------------------------
__global__ void __launch_bounds__(256) k_h(const float* __restrict__ x,
                                           const float* __restrict__ W1) {
    __shared__ float sW1[FIN * CC];
    __shared__ float sX[8][FIN];
    int t = threadIdx.x;
    int n0 = blockIdx.x * 8;
    for (int i = t; i < FIN * CC; i += 256) sW1[i] = W1[i];
    for (int i = t; i < 8 * FIN; i += 256)
        sX[i >> 8][i & 255] = x[(n0 + (i >> 8)) * FIN + (i & 255)];
    __syncthreads();
    int ty = t >> 5, tx = t & 31;
    float acc = 0.f;
#pragma unroll 8
    for (int f = 0; f < FIN; f++) acc += sX[ty][f] * sW1[f * CC + tx];
    g_h[(n0 + ty) * CC + tx] = 0.25f * acc;
}

// ---------------------------------------------------------------------------
// weight split for k_sc_mm
// ---------------------------------------------------------------------------
__global__ void k_bsplit(const float* __restrict__ Wsc) {
    int idx = blockIdx.x * blockDim.x + threadIdx.x;
    if (idx >= 1024 * 256) return;
    float v = Wsc[idx];
    __nv_bfloat16 hi = __float2bfloat16(v);
    g_Bhi[idx] = hi;
    g_Blo[idx] = __float2bfloat16(v - __bfloat162float(hi));
}

// ---------------------------------------------------------------------------
// tensor-core k_sc (R8, proven): out = xa @ Wsc, bf16 split
// ---------------------------------------------------------------------------
#define ASTR 40
#define BSTR 264

__global__ void __launch_bounds__(256) k_sc_mm(const float* __restrict__ x,
                                               const float* __restrict__ attrs,
                                               float* __restrict__ out) {
    extern __shared__ char smem[];
    __nv_bfloat16* sAhi = (__nv_bfloat16*)smem;
    __nv_bfloat16* sAlo = sAhi + 64 * ASTR;
    __nv_bfloat16* sBhi = sAlo + 64 * ASTR;
    __nv_bfloat16* sBlo = sBhi + 32 * BSTR;
    float* sOut = (float*)smem;

    int t = threadIdx.x;
    int wid = t >> 5;
    int warp_m = wid >> 2;
    int warp_n = wid & 3;
    int n0 = blockIdx.x * 64;

    wmma::fragment<wmma::accumulator, 16, 16, 16, float> acc[2][4];
#pragma unroll
    for (int im = 0; im < 2; im++)
#pragma unroll
        for (int jn = 0; jn < 4; jn++) wmma::fill_fragment(acc[im][jn], 0.0f);

    for (int kc = 0; kc < FIN * SSP; kc += 32) {
        for (int i = t; i < 64 * 32; i += 256) {
            int n = i >> 5, kk = i & 31;
            int k = kc + kk;
            int nn = n0 + n;
            float a = 0.f;
            if (nn < NN) a = x[nn * FIN + (k >> 2)] * attrs[nn * SSP + (k & 3)];
            __nv_bfloat16 hi = __float2bfloat16(a);
            sAhi[n * ASTR + kk] = hi;
            sAlo[n * ASTR + kk] = __float2bfloat16(a - __bfloat162float(hi));
        }
        for (int i = t; i < 32 * 256; i += 256) {
            int r = i >> 8, c = i & 255;
            sBhi[r * BSTR + c] = g_Bhi[(kc + r) * 256 + c];
            sBlo[r * BSTR + c] = g_Blo[(kc + r) * 256 + c];
        }
        __syncthreads();

#pragma unroll
        for (int kf = 0; kf < 2; kf++) {
            wmma::fragment<wmma::matrix_a, 16, 16, 16, __nv_bfloat16,
                           wmma::row_major> ahi[2], alo[2];
#pragma unroll
            for (int im = 0; im < 2; im++) {
                wmma::load_matrix_sync(ahi[im],
                    sAhi + (warp_m * 32 + 16 * im) * ASTR + kf * 16, ASTR);
                wmma::load_matrix_sync(alo[im],
                    sAlo + (warp_m * 32 + 16 * im) * ASTR + kf * 16, ASTR);
            }
#pragma unroll
            for (int jn = 0; jn < 4; jn++) {
                wmma::fragment<wmma::matrix_b, 16, 16, 16, __nv_bfloat16,
                               wmma::row_major> bhi, blo;
                wmma::load_matrix_sync(bhi,
                    sBhi + (kf * 16) * BSTR + warp_n * 64 + 16 * jn, BSTR);
                wmma::load_matrix_sync(blo,
                    sBlo + (kf * 16) * BSTR + warp_n * 64 + 16 * jn, BSTR);
#pragma unroll
                for (int im = 0; im < 2; im++) {
                    wmma::mma_sync(acc[im][jn], ahi[im], bhi, acc[im][jn]);
                    wmma::mma_sync(acc[im][jn], ahi[im], blo, acc[im][jn]);
                    wmma::mma_sync(acc[im][jn], alo[im], bhi, acc[im][jn]);
                }
            }
        }
        __syncthreads();
    }

    for (int half = 0; half < 2; half++) {
        if (warp_m == half) {
#pragma unroll
            for (int im = 0; im < 2; im++)
#pragma unroll
                for (int jn = 0; jn < 4; jn++)
                    wmma::store_matrix_sync(
                        sOut + (16 * im) * BSTR + warp_n * 64 + 16 * jn,
                        acc[im][jn], BSTR, wmma::mem_row_major);
        }
        __syncthreads();
        for (int i = t; i < 32 * 256; i += 256) {
            int r = i >> 8, c = i & 255;
            int nn = n0 + half * 32 + r;
            if (nn < NN) out[(long long)nn * FOUT + c] = sOut[r * BSTR + c];
        }
        __syncthreads();
    }
}

// ---------------------------------------------------------------------------
// fused edge kernel: 256 threads, 64-edge sorted tiles, Wm3 via __ldg (L1),
// 2 CTAs/SM (smem 64 KB)
// ---------------------------------------------------------------------------
#define ACTP 65
#define TSTR 66

__global__ void __launch_bounds__(256, 2) k_edge(
    const float* __restrict__ eeG, const float* __restrict__ shG,
    const int* __restrict__ dstG, const int* __restrict__ srcG,
    const float* __restrict__ Wm1, const float* __restrict__ Wm2,
    const float* __restrict__ Wm3) {
    extern __shared__ float sm[];
    float* sWm1  = sm;                       // 512
    float* sWm2  = sWm1 + 512;               // 4096
    float* sAct  = sWm2 + 4096;              // 64*65
    float* sActT = sAct + 64 * ACTP;         // 64*66
    float* sEE   = sActT + 64 * TSTR;        // 512
    float* sSH   = sEE + 512;                // 576
    float* sHs   = sSH + 576;                // 2048
    int*   sDst  = (int*)(sHs + 2048);       // 64
    int*   sSrc  = sDst + 64;                // 64
    int*   sEid  = sSrc + 64;                // 64

    int t = threadIdx.x;
    for (int i = t; i < 512;  i += 256) sWm1[i] = Wm1[i];
    for (int i = t; i < 4096; i += 256) sWm2[i] = Wm2[i];
    __syncthreads();

    const int tx = t & 31, ty = t >> 5;
    const int e_loc = t & 63;
    const int j0 = (t >> 6) * 16;

    for (int tile = blockIdx.x; tile < EE / 64; tile += gridDim.x) {
        int e0g = tile * 64;
        if (t < 64) {
            int eg = g_perm[e0g + t];
            sEid[t] = eg;
            sDst[t] = dstG[eg];
            sSrc[t] = srcG[eg];
        }
        __syncthreads();
        for (int i = t; i < 64 * BB; i += 256) {
            int e = i >> 3, b = i & 7;
            sEE[i] = eeG[sEid[e] * BB + b];
        }
        for (int i = t; i < 64 * AA; i += 256) {
            int e = i / AA, a = i - AA * e;
            sSH[i] = shG[sEid[e] * AA + a];
        }
        for (int i = t; i < 64 * CC; i += 256) {
            int e = i >> 5, c = i & 31;
            sHs[i] = g_h[sSrc[e] * CC + c];
        }
        __syncthreads();

        // phase 1: h1 = silu(ee @ Wm1)
        {
            float acc[16];
#pragma unroll
            for (int j = 0; j < 16; j++) acc[j] = 0.f;
#pragma unroll
            for (int b = 0; b < BB; b++) {
                float v = sEE[e_loc * BB + b];
#pragma unroll
                for (int j = 0; j < 16; j++) acc[j] += v * sWm1[b * HH + j0 + j];
            }
#pragma unroll
            for (int j = 0; j < 16; j++) sAct[e_loc * ACTP + j0 + j] = silu_f(acc[j]);
        }
        __syncthreads();

        // phase 2: h2 = silu(h1 @ Wm2), transposed output
        {
            float acc[16];
#pragma unroll
            for (int j = 0; j < 16; j++) acc[j] = 0.f;
#pragma unroll 8
            for (int k = 0; k < HH; k++) {
                float v = sAct[e_loc * ACTP + k];
#pragma unroll
                for (int j = 0; j < 16; j++) acc[j] += v * sWm2[k * HH + j0 + j];
            }
#pragma unroll
            for (int j = 0; j < 16; j++)
                sActT[(j0 + j) * TSTR + e_loc] = silu_f(acc[j]);
        }
        __syncthreads();

        // phase 3: edge-pair FFMA2; B = Wm3 via __ldg (L1-resident, coalesced)
        {
            unsigned long long acc2[4][9];
#pragma unroll
            for (int m = 0; m < 4; m++)
#pragma unroll
                for (int j = 0; j < 9; j++) acc2[m][j] = 0ull;

#pragma unroll 2
            for (int k = 0; k < HH; k++) {
                unsigned long long a2[4];
#pragma unroll
                for (int m = 0; m < 4; m++)
                    a2[m] = lds64(&sActT[k * TSTR + 8 * ty + 2 * m]);
#pragma unroll
                for (int j = 0; j < 9; j++) {
                    float b = __ldg(&Wm3[k * WN + tx + 32 * j]);
                    unsigned long long bb = pack2(b, b);
#pragma unroll
                    for (int m = 0; m < 4; m++) fma2(acc2[m][j], a2[m], bb);
                }
            }

            // epilogue: run-length reduce + scatter (c,a via mul-shift /9)
            float racc[9];
            int cjl[9], ajl[9];
#pragma unroll
            for (int j = 0; j < 9; j++) {
                racc[j] = 0.f;
                int o = tx + 32 * j;
                int c = (o * 7282) >> 16;   // floor(o/9) for o<512
                cjl[j] = c;
                ajl[j] = o - 9 * c;
            }
            int cur = sDst[8 * ty];

#pragma unroll
            for (int m = 0; m < 4; m++) {
                int e0 = 8 * ty + 2 * m;
                int e1 = e0 + 1;
                const float* hs0 = &sHs[e0 * CC];
                const float* hs1 = &sHs[e1 * CC];
                const float* sh0 = &sSH[e0 * AA];
                const float* sh1 = &sSH[e1 * AA];
                int d0 = sDst[e0], d1 = sDst[e1];
                if (d0 != cur) {
                    float* dp = g_agg + (long long)cur * WN;
#pragma unroll
                    for (int j = 0; j < 9; j++) {
                        atomicAdd(dp + tx + 32 * j, racc[j]);
                        racc[j] = 0.f;
                    }
                    cur = d0;
                }
#pragma unroll
                for (int j = 0; j < 9; j++) {
                    float2 w = unpack2(acc2[m][j]);
                    racc[j] += w.x * hs0[cjl[j]] * sh0[ajl[j]];
                }
                if (d1 != cur) {
                    float* dp = g_agg + (long long)cur * WN;
#pragma unroll
                    for (int j = 0; j < 9; j++) {
                        atomicAdd(dp + tx + 32 * j, racc[j]);
                        racc[j] = 0.f;
                    }
                    cur = d1;
                }
#pragma unroll
                for (int j = 0; j < 9; j++) {
                    float2 w = unpack2(acc2[m][j]);
                    racc[j] += w.y * hs1[cjl[j]] * sh1[ajl[j]];
                }
            }
            {
                float* dp = g_agg + (long long)cur * WN;
#pragma unroll
                for (int j = 0; j < 9; j++) atomicAdd(dp + tx + 32 * j, racc[j]);
            }
        }
        __syncthreads();
    }
}

// ---------------------------------------------------------------------------
// out = silu(agg @ W2) + sc_out (R1 scalar, proven)
// ---------------------------------------------------------------------------
__global__ void __launch_bounds__(256) k_final(const float* __restrict__ W2,
                                               float* __restrict__ out) {
    __shared__ float sA[32][65];
    __shared__ float sB[32][64];
    int t = threadIdx.x;
    int n0 = blockIdx.x * 64;
    int o0 = blockIdx.y * 64;
    int tr = t >> 4, tc = t & 15;
    float acc[4][4];
#pragma unroll
    for (int i = 0; i < 4; i++)
#pragma unroll
        for (int j = 0; j < 4; j++) acc[i][j] = 0.f;

    for (int kc = 0; kc < WN; kc += 32) {
        for (int i = t; i < 64 * 32; i += 256) {
            int n = i >> 5, kk = i & 31;
            int nn = n0 + n;
            sA[kk][n] = (nn < NN) ? g_agg[(long long)nn * WN + kc + kk] : 0.f;
        }
        for (int i = t; i < 32 * 64; i += 256) {
            int kk = i >> 6, o = i & 63;
            sB[kk][o] = W2[(kc + kk) * FOUT + o0 + o];
        }
        __syncthreads();
#pragma unroll 8
        for (int k = 0; k < 32; k++) {
            float a[4], b[4];
#pragma unroll
            for (int i = 0; i < 4; i++) a[i] = sA[k][tr * 4 + i];
#pragma unroll
            for (int j = 0; j < 4; j++) b[j] = sB[k][tc * 4 + j];
#pragma unroll
            for (int i = 0; i < 4; i++)
#pragma unroll
                for (int j = 0; j < 4; j++) acc[i][j] += a[i] * b[j];
        }
        __syncthreads();
    }
#pragma unroll
    for (int i = 0; i < 4; i++) {
        int nn = n0 + tr * 4 + i;
        if (nn >= NN) continue;
#pragma unroll
        for (int j = 0; j < 4; j++) {
            int o = o0 + tc * 4 + j;
            out[nn * FOUT + o] = silu_f(acc[i][j]) + out[nn * FOUT + o];
        }
    }
}

// ---------------------------------------------------------------------------
extern "C" void kernel_launch(void* const* d_in, const int* in_sizes, int n_in,
                              void* d_out, int out_size) {
    const float* x     = (const float*)d_in[0];
    const float* attrs = (const float*)d_in[1];
    const float* ee    = (const float*)d_in[2];
    const float* sh    = (const float*)d_in[3];
    const int*   eidx  = (const int*)d_in[4];
    const float* W1    = (const float*)d_in[5];
    const float* Wm1   = (const float*)d_in[6];
    const float* Wm2   = (const float*)d_in[7];
    const float* Wm3   = (const float*)d_in[8];
    const float* W2    = (const float*)d_in[9];
    const float* Wsc   = (const float*)d_in[10];
    float* out = (float*)d_out;

    const int* dst = eidx;
    const int* src = eidx + EE;

    k_zero<<<1024, 256>>>();
    k_hist<<<400, 256>>>(dst);
    k_scan<<<1, 1024>>>();
    k_place<<<400, 256>>>(dst);

    k_h<<<NN / 8, 256>>>(x, W1);
    k_bsplit<<<1024, 256>>>(Wsc);

    const int sc_smem = (2 * 64 * ASTR + 2 * 32 * BSTR) * 2 + 256;
    cudaFuncSetAttribute(k_sc_mm, cudaFuncAttributeMaxDynamicSharedMemorySize, sc_smem);
    k_sc_mm<<<(NN + 63) / 64, 256, sc_smem>>>(x, attrs, out);

    const int edge_smem =
        (512 + 4096 + 64 * ACTP + 64 * TSTR + 512 + 576 + 2048) * 4 +
        3 * 64 * 4 + 256;
    cudaFuncSetAttribute(k_edge, cudaFuncAttributeMaxDynamicSharedMemorySize, edge_smem);
    k_edge<<<304, 256, edge_smem>>>(ee, sh, dst, src, Wm1, Wm2, Wm3);

    dim3 gf((NN + 63) / 64, 4);
    k_final<<<gf, 256>>>(W2, out);
}